// round 14
// baseline (speedup 1.0000x reference)
#include <cuda_runtime.h>
#include <cuda_fp16.h>
#include <cstdint>

namespace {
constexpr int B = 4, L = 2048, D = 1024, H = 16, DH = 64;
constexpr int BH = B * H;    // 64
constexpr int ML = B * L;    // 8192
constexpr float LOG2E = 1.4426950408889634f;
constexpr size_t NX = (size_t)ML * D;        // elems per q/k/v
constexpr size_t NW = (size_t)D * D;         // elems per W
constexpr int MW = L / 32;                   // mask words per row
constexpr int ST = 72;                       // smem row stride (halves) = 144 B
}

__device__ __half g_Qh[(size_t)B * H * L * DH];   // [bh, l, d]
__device__ __half g_Kh[(size_t)B * H * L * DH];   // [bh, l, d]
__device__ __half g_Vt[(size_t)B * H * DH * L];   // [bh, d, l] (transposed)
__device__ __half g_OutH[(size_t)B * L * H * DH]; // [b*L, h*64]
__device__ float2 g_stats[(size_t)BH * L];        // per row: (m_off, inv)
__device__ __half g_xR[3 * NX];                   // fp16 q|k|v
__device__ __half g_WT[4 * NW];                   // W^T fp16: [n][k]
__device__ uint32_t g_mbits[(size_t)B * L * MW];  // packed mask bits

// ---------------------------------------------------------------------------
// streams/events for capture-legal fork-join overlap (static init)
// ---------------------------------------------------------------------------
namespace {
struct OverlapRes {
    cudaStream_t s1, s2;
    cudaEvent_t evRoot, evPre, evT, evM, evV;
    OverlapRes() {
        cudaStreamCreateWithFlags(&s1, cudaStreamNonBlocking);
        cudaStreamCreateWithFlags(&s2, cudaStreamNonBlocking);
        cudaEventCreateWithFlags(&evRoot, cudaEventDisableTiming);
        cudaEventCreateWithFlags(&evPre,  cudaEventDisableTiming);
        cudaEventCreateWithFlags(&evT,    cudaEventDisableTiming);
        cudaEventCreateWithFlags(&evM,    cudaEventDisableTiming);
        cudaEventCreateWithFlags(&evV,    cudaEventDisableTiming);
    }
};
OverlapRes g_ov;
}

// ---------------------------------------------------------------------------
// helpers
// ---------------------------------------------------------------------------
__device__ __forceinline__ void mma16(float* c, const uint32_t* a, const uint32_t* b) {
    asm("mma.sync.aligned.m16n8k16.row.col.f32.f16.f16.f32 "
        "{%0,%1,%2,%3},{%4,%5,%6,%7},{%8,%9},{%0,%1,%2,%3};"
        : "+f"(c[0]), "+f"(c[1]), "+f"(c[2]), "+f"(c[3])
        : "r"(a[0]), "r"(a[1]), "r"(a[2]), "r"(a[3]), "r"(b[0]), "r"(b[1]));
}
__device__ __forceinline__ void ldsm4(uint32_t* r, uint32_t addr) {
    asm volatile("ldmatrix.sync.aligned.m8n8.x4.shared.b16 {%0,%1,%2,%3}, [%4];"
                 : "=r"(r[0]), "=r"(r[1]), "=r"(r[2]), "=r"(r[3]) : "r"(addr));
}
__device__ __forceinline__ uint32_t smaddr(const void* p) {
    return (uint32_t)__cvta_generic_to_shared(p);
}
__device__ __forceinline__ void cpa16(uint32_t dst, const void* src) {
    asm volatile("cp.async.ca.shared.global [%0], [%1], 16;\n" :: "r"(dst), "l"(src));
}
__device__ __forceinline__ void cp_commit() {
    asm volatile("cp.async.commit_group;\n");
}
template <int N> __device__ __forceinline__ void cp_wait() {
    asm volatile("cp.async.wait_group %0;\n" :: "n"(N));
}
__device__ __forceinline__ void st_cs_f2(float* p, float x, float y) {
    asm volatile("st.global.cs.v2.f32 [%0], {%1, %2};"
                 :: "l"(p), "f"(x), "f"(y) : "memory");
}

// ---------------------------------------------------------------------------
// Pre-convert q/k/v to fp16 (rne), once.
// ---------------------------------------------------------------------------
__global__ __launch_bounds__(256) void preround(
    const float4* __restrict__ q, const float4* __restrict__ k,
    const float4* __restrict__ v)
{
    const size_t NX4 = NX / 4;
    size_t i = (size_t)blockIdx.x * 256 + threadIdx.x;
    const float4* src = (i < NX4) ? q : (i < 2 * NX4) ? k : v;
    size_t off = (i < NX4) ? i : (i < 2 * NX4) ? i - NX4 : i - 2 * NX4;
    float4 x = src[off];
    ((__half2*)g_xR)[2 * i]     = __floats2half2_rn(x.x, x.y);
    ((__half2*)g_xR)[2 * i + 1] = __floats2half2_rn(x.z, x.w);
}

// ---------------------------------------------------------------------------
// Transpose + convert weights: g_WT[z][n][k] = fp16(W_z[k][n]).
// ---------------------------------------------------------------------------
__global__ __launch_bounds__(256) void transposeW(
    const float* __restrict__ wq, const float* __restrict__ wk,
    const float* __restrict__ wv, const float* __restrict__ wfc)
{
    __shared__ float t[32][33];
    const int z = blockIdx.z;
    const float* src = (z == 0) ? wq : (z == 1) ? wk : (z == 2) ? wv : wfc;
    const int k0 = blockIdx.y * 32, n0 = blockIdx.x * 32;
    const int x = threadIdx.x & 31, y = threadIdx.x >> 5;  // 32 x 8
#pragma unroll
    for (int j = 0; j < 4; j++)
        t[y + j * 8][x] = src[(size_t)(k0 + y + j * 8) * D + n0 + x];
    __syncthreads();
#pragma unroll
    for (int j = 0; j < 4; j++)
        g_WT[(size_t)z * NW + (size_t)(n0 + y + j * 8) * D + k0 + x] =
            __float2half_rn(t[x][y + j * 8]);
}

// ---------------------------------------------------------------------------
// Pack int32 mask -> bitmask.
// ---------------------------------------------------------------------------
__global__ __launch_bounds__(256) void packmask(const int* __restrict__ mask)
{
    size_t i = (size_t)blockIdx.x * 256 + threadIdx.x;
    int mv = mask[i];
    uint32_t bal = __ballot_sync(0xffffffffu, mv != 0);
    if ((threadIdx.x & 31) == 0) g_mbits[i >> 5] = bal;
}

// ---------------------------------------------------------------------------
// GEMM 1: QKV projections (z = blockIdx.z + zbase).  fp16 mma m16n8k16.
// 128 thr, 4 warps, warp tile 64x64, ktile 64, cp.async 2-stage.
// V stored TRANSPOSED [bh, d, l].
// ---------------------------------------------------------------------------
__global__ __launch_bounds__(128, 2) void gemm_proj_all(
    const float* __restrict__ bq, const float* __restrict__ bk,
    const float* __restrict__ bv,
    __half* __restrict__ Qh, __half* __restrict__ Kh, __half* __restrict__ Vt,
    int zbase)
{
    const int z = blockIdx.z + zbase;
    const __half* X = g_xR + (size_t)z * NX;
    const __half* WT = g_WT + (size_t)z * NW;
    const float* bias = (z == 0) ? bq : (z == 1) ? bk : bv;
    const float scale = (z == 0) ? 0.125f : 1.0f;

    extern __shared__ __half dynh[];
    __half* As = dynh;                  // 2 x [128][72]
    __half* Bs = dynh + 2 * 9216;       // 2 x [128][72]

    const int tid = threadIdx.x;
    const int lane = tid & 31, w = tid >> 5;
    const int g = lane >> 2, tg = lane & 3;
    const int wm = (w >> 1) * 64, wn = (w & 1) * 64;
    const int m0 = blockIdx.y * 128, n0 = blockIdx.x * 128;

    const uint32_t a_base0 = smaddr(As) +
        (((wm + (lane & 15)) * ST + (lane >> 4) * 8) << 1);
    const uint32_t b_base0 = smaddr(Bs) +
        (((wn + (lane & 15)) * ST + (lane >> 4) * 8) << 1);

    auto issue = [&](int s, int k0) {
#pragma unroll
        for (int t = 0; t < 8; t++) {           // A: 128x64 halves = 16 KB
            int idx = tid + t * 128;
            int row = idx >> 3, cc = (idx & 7) * 8;
            cpa16(smaddr(As + s * 9216 + row * ST + cc),
                  X + (size_t)(m0 + row) * D + k0 + cc);
        }
#pragma unroll
        for (int t = 0; t < 8; t++) {           // B: 128x64 halves
            int idx = tid + t * 128;
            int row = idx >> 3, cc = (idx & 7) * 8;
            cpa16(smaddr(Bs + s * 9216 + row * ST + cc),
                  WT + (size_t)(n0 + row) * D + k0 + cc);
        }
    };

    float c[4][8][4];
#pragma unroll
    for (int mi = 0; mi < 4; mi++)
#pragma unroll
        for (int ni = 0; ni < 8; ni++)
#pragma unroll
            for (int r = 0; r < 4; r++) c[mi][ni][r] = 0.f;

    issue(0, 0); cp_commit();

    for (int t = 0; t < 16; t++) {
        if (t + 1 < 16) { issue((t + 1) & 1, (t + 1) * 64); cp_commit(); cp_wait<1>(); }
        else cp_wait<0>();
        __syncthreads();
        const uint32_t aB = a_base0 + (t & 1) * 9216 * 2;
        const uint32_t bB = b_base0 + (t & 1) * 9216 * 2;
#pragma unroll
        for (int ks = 0; ks < 4; ks++) {
            const int kk = ks * 16;
            uint32_t a[4][4], bb[8][2];
#pragma unroll
            for (int mi = 0; mi < 4; mi++)
                ldsm4(a[mi], aB + ((mi * 16 * ST + kk) << 1));
#pragma unroll
            for (int pr = 0; pr < 4; pr++) {
                uint32_t rr[4];
                ldsm4(rr, bB + ((pr * 16 * ST + kk) << 1));
                bb[2 * pr][0] = rr[0]; bb[2 * pr][1] = rr[2];
                bb[2 * pr + 1][0] = rr[1]; bb[2 * pr + 1][1] = rr[3];
            }
#pragma unroll
            for (int mi = 0; mi < 4; mi++)
#pragma unroll
                for (int ni = 0; ni < 8; ni++)
                    mma16(c[mi][ni], a[mi], bb[ni]);
        }
        __syncthreads();
    }
    const int bblk = m0 / L, lbase = m0 % L;
    if (z < 2) {
        __half* OutHeads = (z == 0) ? Qh : Kh;
#pragma unroll
        for (int mi = 0; mi < 4; mi++)
#pragma unroll
            for (int r = 0; r < 2; r++) {
                int l = lbase + wm + mi * 16 + g + r * 8;
#pragma unroll
                for (int ni = 0; ni < 8; ni++) {
                    int n = n0 + wn + ni * 8 + tg * 2;
                    int h = n >> 6, d = n & 63;
                    *(__half2*)&OutHeads[(((size_t)bblk * H + h) * L + l) * DH + d] =
                        __floats2half2_rn((c[mi][ni][r * 2 + 0] + bias[n]) * scale,
                                          (c[mi][ni][r * 2 + 1] + bias[n + 1]) * scale);
                }
            }
    } else {
#pragma unroll
        for (int mi = 0; mi < 4; mi++)
#pragma unroll
            for (int r = 0; r < 2; r++) {
                int l = lbase + wm + mi * 16 + g + r * 8;
#pragma unroll
                for (int ni = 0; ni < 8; ni++) {
                    int n = n0 + wn + ni * 8 + tg * 2;
                    int h = n >> 6, d = n & 63;
                    size_t base = ((size_t)(bblk * H + h) * DH + d) * L + l;
                    Vt[base]     = __float2half_rn(c[mi][ni][r * 2 + 0] + bias[n]);
                    Vt[base + L] = __float2half_rn(c[mi][ni][r * 2 + 1] + bias[n + 1]);
                }
            }
    }
}

// ---------------------------------------------------------------------------
// Pass 1: per-row expsum via h2exp (fp16x2 MUFU, 2 vals/op).  No max pass.
// ---------------------------------------------------------------------------
__global__ __launch_bounds__(256, 2) void attn_stats()
{
    extern __shared__ __half dynh[];
    __half* Qs = dynh;                        // [128][72]
    __half* Ks = dynh + 9216;                 // 2 x [128][72]
    float* red = (float*)(dynh + 3 * 9216);   // [128][4]

    const int tid = threadIdx.x;
    const int lane = tid & 31, w = tid >> 5;
    const int g = lane >> 2, tg = lane & 3;
    const int wm = (w >> 2) * 64, wn = (w & 3) * 32;
    const int bh = blockIdx.y, b = bh >> 4;
    const int i0 = blockIdx.x * 128;
    const __half* Qb = g_Qh + (size_t)bh * L * DH;
    const __half* Kb = g_Kh + (size_t)bh * L * DH;
    const uint32_t* mb = g_mbits + (size_t)b * L * MW;

    const uint32_t q_base = smaddr(Qs) +
        (((wm + (lane & 15)) * ST + (lane >> 4) * 8) << 1);
    const uint32_t k_base0 = smaddr(Ks) +
        (((wn + (lane & 15)) * ST + (lane >> 4) * 8) << 1);

    auto issueK = [&](int s, int j0) {
#pragma unroll
        for (int t = 0; t < 4; t++) {
            int idx = tid + t * 256;
            int row = idx >> 3, cc = (idx & 7) * 8;
            cpa16(smaddr(Ks + s * 9216 + row * ST + cc),
                  Kb + (size_t)(j0 + row) * DH + cc);
        }
    };
#pragma unroll
    for (int t = 0; t < 4; t++) {
        int idx = tid + t * 256;
        int row = idx >> 3, cc = (idx & 7) * 8;
        cpa16(smaddr(Qs + row * ST + cc), Qb + (size_t)(i0 + row) * DH + cc);
    }
    issueK(0, 0); cp_commit();

    float l_run[4][2];
#pragma unroll
    for (int mi = 0; mi < 4; mi++)
#pragma unroll
        for (int r = 0; r < 2; r++) l_run[mi][r] = 0.f;

    for (int jt = 0; jt < 16; jt++) {
        const int j0 = jt * 128;
        if (jt + 1 < 16) { issueK((jt + 1) & 1, (jt + 1) * 128); cp_commit(); cp_wait<1>(); }
        else cp_wait<0>();
        __syncthreads();
        const uint32_t kB = k_base0 + (jt & 1) * 9216 * 2;

        float c[4][4][4];
#pragma unroll
        for (int mi = 0; mi < 4; mi++)
#pragma unroll
            for (int ni = 0; ni < 4; ni++)
#pragma unroll
                for (int r = 0; r < 4; r++) c[mi][ni][r] = 0.f;
#pragma unroll
        for (int ks = 0; ks < 4; ks++) {
            const int kk = ks * 16;
            uint32_t a[4][4], bb[4][2];
#pragma unroll
            for (int mi = 0; mi < 4; mi++)
                ldsm4(a[mi], q_base + ((mi * 16 * ST + kk) << 1));
#pragma unroll
            for (int pr = 0; pr < 2; pr++) {
                uint32_t rr[4];
                ldsm4(rr, kB + ((pr * 16 * ST + kk) << 1));
                bb[2 * pr][0] = rr[0]; bb[2 * pr][1] = rr[2];
                bb[2 * pr + 1][0] = rr[1]; bb[2 * pr + 1][1] = rr[3];
            }
#pragma unroll
            for (int mi = 0; mi < 4; mi++)
#pragma unroll
                for (int ni = 0; ni < 4; ni++)
                    mma16(c[mi][ni], a[mi], bb[ni]);
        }

        // masked exp-sum via fp16x2 exp + HFMA2 against {0,1} mask half2
#pragma unroll
        for (int mi = 0; mi < 4; mi++)
#pragma unroll
            for (int r = 0; r < 2; r++) {
                int i = i0 + wm + mi * 16 + g + r * 8;
                uint32_t word = mb[(size_t)i * MW + ((j0 + wn) >> 5)];
                __half2 acc2 = __float2half2_rn(0.f);
#pragma unroll
                for (int ni = 0; ni < 4; ni++) {
                    int bit = ni * 8 + tg * 2;
                    __half2 sh = __floats2half2_rn(c[mi][ni][r * 2 + 0],
                                                   c[mi][ni][r * 2 + 1]);
                    __half2 e = h2exp(sh);
                    uint32_t m2 = (((word >> bit) & 1u) ? 0x3C00u : 0u)
                                | (((word >> (bit + 1)) & 1u) ? 0x3C000000u : 0u);
                    acc2 = __hfma2(e, *(__half2*)&m2, acc2);
                }
                l_run[mi][r] += __low2float(acc2) + __high2float(acc2);
            }
        __syncthreads();
    }
#pragma unroll
    for (int mi = 0; mi < 4; mi++)
#pragma unroll
        for (int r = 0; r < 2; r++) {
            float l = l_run[mi][r];
            l += __shfl_xor_sync(0xffffffffu, l, 1);
            l += __shfl_xor_sync(0xffffffffu, l, 2);
            if ((lane & 3) == 0)
                red[(wm + mi * 16 + g + r * 8) * 4 + (w & 3)] = l;
        }
    __syncthreads();
    if (tid < 128) {
        float l = red[tid * 4 + 0] + red[tid * 4 + 1]
                + red[tid * 4 + 2] + red[tid * 4 + 3];
        g_stats[(size_t)bh * L + i0 + tid] =
            (l == 0.f) ? make_float2(-1e9f, 1.f / (float)L)
                       : make_float2(0.f, 1.f / l);
    }
}

// ---------------------------------------------------------------------------
// Pass 2: recompute scores, normalize (h2exp), write att once (.cs), O = P@V.
// ---------------------------------------------------------------------------
__global__ __launch_bounds__(256, 1) void attn_pv(float* __restrict__ att)
{
    extern __shared__ __half dynh[];
    __half* Ks = dynh;                    // 2 x [64][72] = 2 x 4608
    __half* Vs = dynh + 2 * 4608;         // 2 x [64][72]
    __half* Ps = dynh + 4 * 4608;         // [128][72]

    const int tid = threadIdx.x;
    const int lane = tid & 31, w = tid >> 5;
    const int g = lane >> 2, tg = lane & 3;
    const int rg = w >> 1;                 // rows rg*32..+32
    const int jg = w & 1;                  // scores j half
    const int dg = w & 1;                  // PV d half
    const int bh = blockIdx.y, b = bh >> 4, h = bh & 15;
    const int i0 = blockIdx.x * 128;
    const __half* Qb = g_Qh + (size_t)bh * L * DH;
    const __half* Kb = g_Kh + (size_t)bh * L * DH;
    const __half* Vb = g_Vt + (size_t)bh * DH * L;
    const uint32_t* mb = g_mbits + (size_t)b * L * MW;
    float* arow = att + (size_t)bh * L * L;

    // stage Q (128x64) into Ps
#pragma unroll
    for (int t = 0; t < 4; t++) {
        int idx = tid + t * 256;
        int row = idx >> 3, cc = (idx & 7) * 8;
        cpa16(smaddr(Ps + row * ST + cc), Qb + (size_t)(i0 + row) * DH + cc);
    }
    cp_commit();

    auto issueKV = [&](int s, int j0) {
#pragma unroll
        for (int t = 0; t < 2; t++) {           // K: 64x64 halves
            int idx = tid + t * 256;
            int row = idx >> 3, cc = (idx & 7) * 8;
            cpa16(smaddr(Ks + s * 4608 + row * ST + cc),
                  Kb + (size_t)(j0 + row) * DH + cc);
        }
#pragma unroll
        for (int t = 0; t < 2; t++) {           // V: 64 d-rows x 64 j
            int idx = tid + t * 256;
            int row = idx >> 3, cc = (idx & 7) * 8;
            cpa16(smaddr(Vs + s * 4608 + row * ST + cc),
                  Vb + (size_t)row * L + j0 + cc);
        }
    };
    issueKV(0, 0); cp_commit();

    cp_wait<1>();
    __syncthreads();

    uint32_t qf[2][4][4];
    {
        const uint32_t qb = smaddr(Ps) +
            (((rg * 32 + (lane & 15)) * ST + (lane >> 4) * 8) << 1);
#pragma unroll
        for (int mi = 0; mi < 2; mi++)
#pragma unroll
            for (int ks = 0; ks < 4; ks++)
                ldsm4(qf[mi][ks], qb + ((mi * 16 * ST + ks * 16) << 1));
    }

    float sm[2][2], sinv[2][2];
    __half2 sinvh[2][2];
#pragma unroll
    for (int mi = 0; mi < 2; mi++)
#pragma unroll
        for (int r = 0; r < 2; r++) {
            float2 s = g_stats[(size_t)bh * L + i0 + rg * 32 + mi * 16 + g + r * 8];
            sm[mi][r] = s.x; sinv[mi][r] = s.y;
            sinvh[mi][r] = __float2half2_rn(s.y);
        }

    const uint32_t k_base0 = smaddr(Ks) +
        (((jg * 32 + (lane & 15)) * ST + (lane >> 4) * 8) << 1);
    const uint32_t v_base0 = smaddr(Vs) +
        (((dg * 32 + (lane & 15)) * ST + (lane >> 4) * 8) << 1);
    const uint32_t p_base = smaddr(Ps) +
        (((rg * 32 + (lane & 15)) * ST + (lane >> 4) * 8) << 1);

    float co[2][4][4];
#pragma unroll
    for (int mi = 0; mi < 2; mi++)
#pragma unroll
        for (int ni = 0; ni < 4; ni++)
#pragma unroll
            for (int r = 0; r < 4; r++) co[mi][ni][r] = 0.f;

    for (int ch = 0; ch < 32; ch++) {
        if (ch + 1 < 32) { issueKV((ch + 1) & 1, (ch + 1) * 64); cp_commit(); cp_wait<1>(); }
        else cp_wait<0>();
        __syncthreads();
        const uint32_t kB = k_base0 + (ch & 1) * 4608 * 2;
        const uint32_t vB = v_base0 + (ch & 1) * 4608 * 2;

        // scores: 32 rows x 32 j (jg half), k = 64
        float c2[2][4][4];
#pragma unroll
        for (int mi = 0; mi < 2; mi++)
#pragma unroll
            for (int ni = 0; ni < 4; ni++)
#pragma unroll
                for (int r = 0; r < 4; r++) c2[mi][ni][r] = 0.f;
#pragma unroll
        for (int ks = 0; ks < 4; ks++) {
            uint32_t bb[4][2];
#pragma unroll
            for (int pr = 0; pr < 2; pr++) {
                uint32_t rr[4];
                ldsm4(rr, kB + ((pr * 16 * ST + ks * 16) << 1));
                bb[2 * pr][0] = rr[0]; bb[2 * pr][1] = rr[2];
                bb[2 * pr + 1][0] = rr[1]; bb[2 * pr + 1][1] = rr[3];
            }
#pragma unroll
            for (int mi = 0; mi < 2; mi++)
#pragma unroll
                for (int ni = 0; ni < 4; ni++)
                    mma16(c2[mi][ni], qf[mi][ks], bb[ni]);
        }

        // mask + exp (h2exp) + normalize; write att (.cs); stage P (fp16)
        const int j0 = ch * 64;
#pragma unroll
        for (int mi = 0; mi < 2; mi++)
#pragma unroll
            for (int r = 0; r < 2; r++) {
                int rl = rg * 32 + mi * 16 + g + r * 8;
                int i = i0 + rl;
                uint32_t word = mb[(size_t)i * MW + ((j0 + jg * 32) >> 5)];
                float m = sm[mi][r], inv = sinv[mi][r];
                __half2 invh = sinvh[mi][r];
#pragma unroll
                for (int ni = 0; ni < 4; ni++) {
                    int bit = ni * 8 + tg * 2;
                    int cl = jg * 32 + bit;
                    float s0 = (word >> bit) & 1 ? c2[mi][ni][r * 2 + 0] : -1e9f;
                    float s1 = (word >> (bit + 1)) & 1 ? c2[mi][ni][r * 2 + 1] : -1e9f;
                    __half2 dh = __floats2half2_rn(s0 - m, s1 - m);
                    __half2 e = h2exp(dh);          // masked -> -inf -> 0
                    float p0 = __low2float(e) * inv;
                    float p1 = __high2float(e) * inv;
                    st_cs_f2(arow + (size_t)i * L + j0 + cl, p0, p1);
                    *(__half2*)&Ps[rl * ST + cl] = __hmul2(e, invh);
                }
            }
        asm volatile("bar.sync %0, %1;" :: "r"(rg + 1), "r"(64) : "memory");

        // PV: 32 rows x 32 d (dg half), k = 64 (j)
#pragma unroll
        for (int ks = 0; ks < 4; ks++) {
            uint32_t a[2][4], bb[4][2];
#pragma unroll
            for (int mi = 0; mi < 2; mi++)
                ldsm4(a[mi], p_base + ((mi * 16 * ST + ks * 16) << 1));
#pragma unroll
            for (int pr = 0; pr < 2; pr++) {
                uint32_t rr[4];
                ldsm4(rr, vB + ((pr * 16 * ST + ks * 16) << 1));
                bb[2 * pr][0] = rr[0]; bb[2 * pr][1] = rr[2];
                bb[2 * pr + 1][0] = rr[1]; bb[2 * pr + 1][1] = rr[3];
            }
#pragma unroll
            for (int mi = 0; mi < 2; mi++)
#pragma unroll
                for (int ni = 0; ni < 4; ni++)
                    mma16(co[mi][ni], a[mi], bb[ni]);
        }
        __syncthreads();
    }
#pragma unroll
    for (int mi = 0; mi < 2; mi++)
#pragma unroll
        for (int ni = 0; ni < 4; ni++) {
            int d = dg * 32 + ni * 8 + tg * 2;
            int row0 = i0 + rg * 32 + mi * 16 + g;
            *(__half2*)&g_OutH[(size_t)(b * L + row0) * D + h * DH + d] =
                __floats2half2_rn(co[mi][ni][0], co[mi][ni][1]);
            *(__half2*)&g_OutH[(size_t)(b * L + row0 + 8) * D + h * DH + d] =
                __floats2half2_rn(co[mi][ni][2], co[mi][ni][3]);
        }
}

// ---------------------------------------------------------------------------
// GEMM 4: out = OutH @ Wfc + bfc + q.  fp16, same structure as proj.
// ---------------------------------------------------------------------------
__global__ __launch_bounds__(128, 2) void gemm_fc(
    const float* __restrict__ Xres,
    const float* __restrict__ bias, float* __restrict__ Out)
{
    extern __shared__ __half dynh[];
    __half* As = dynh;
    __half* Bs = dynh + 2 * 9216;
    const __half* WT = g_WT + 3 * NW;

    const int tid = threadIdx.x;
    const int lane = tid & 31, w = tid >> 5;
    const int g = lane >> 2, tg = lane & 3;
    const int wm = (w >> 1) * 64, wn = (w & 1) * 64;
    const int m0 = blockIdx.y * 128, n0 = blockIdx.x * 128;

    const uint32_t a_base0 = smaddr(As) +
        (((wm + (lane & 15)) * ST + (lane >> 4) * 8) << 1);
    const uint32_t b_base0 = smaddr(Bs) +
        (((wn + (lane & 15)) * ST + (lane >> 4) * 8) << 1);

    auto issue = [&](int s, int k0) {
#pragma unroll
        for (int t = 0; t < 8; t++) {
            int idx = tid + t * 128;
            int row = idx >> 3, cc = (idx & 7) * 8;
            cpa16(smaddr(As + s * 9216 + row * ST + cc),
                  g_OutH + (size_t)(m0 + row) * D + k0 + cc);
        }
#pragma unroll
        for (int t = 0; t < 8; t++) {
            int idx = tid + t * 128;
            int row = idx >> 3, cc = (idx & 7) * 8;
            cpa16(smaddr(Bs + s * 9216 + row * ST + cc),
                  WT + (size_t)(n0 + row) * D + k0 + cc);
        }
    };

    float c[4][8][4];
#pragma unroll
    for (int mi = 0; mi < 4; mi++)
#pragma unroll
        for (int ni = 0; ni < 8; ni++)
#pragma unroll
            for (int r = 0; r < 4; r++) c[mi][ni][r] = 0.f;

    issue(0, 0); cp_commit();

    for (int t = 0; t < 16; t++) {
        if (t + 1 < 16) { issue((t + 1) & 1, (t + 1) * 64); cp_commit(); cp_wait<1>(); }
        else cp_wait<0>();
        __syncthreads();
        const uint32_t aB = a_base0 + (t & 1) * 9216 * 2;
        const uint32_t bB = b_base0 + (t & 1) * 9216 * 2;
#pragma unroll
        for (int ks = 0; ks < 4; ks++) {
            const int kk = ks * 16;
            uint32_t a[4][4], bb[8][2];
#pragma unroll
            for (int mi = 0; mi < 4; mi++)
                ldsm4(a[mi], aB + ((mi * 16 * ST + kk) << 1));
#pragma unroll
            for (int pr = 0; pr < 4; pr++) {
                uint32_t rr[4];
                ldsm4(rr, bB + ((pr * 16 * ST + kk) << 1));
                bb[2 * pr][0] = rr[0]; bb[2 * pr][1] = rr[2];
                bb[2 * pr + 1][0] = rr[1]; bb[2 * pr + 1][1] = rr[3];
            }
#pragma unroll
            for (int mi = 0; mi < 4; mi++)
#pragma unroll
                for (int ni = 0; ni < 8; ni++)
                    mma16(c[mi][ni], a[mi], bb[ni]);
        }
        __syncthreads();
    }
#pragma unroll
    for (int mi = 0; mi < 4; mi++)
#pragma unroll
        for (int r = 0; r < 2; r++) {
            int gm = m0 + wm + mi * 16 + g + r * 8;
#pragma unroll
            for (int ni = 0; ni < 8; ni++) {
                int gn = n0 + wn + ni * 8 + tg * 2;
                float2 res = *(const float2*)(Xres + (size_t)gm * D + gn);
                float2 o;
                o.x = c[mi][ni][r * 2 + 0] + bias[gn]     + res.x;
                o.y = c[mi][ni][r * 2 + 1] + bias[gn + 1] + res.y;
                *(float2*)&Out[(size_t)gm * D + gn] = o;
            }
        }
}

// ---------------------------------------------------------------------------
extern "C" void kernel_launch(void* const* d_in, const int* in_sizes, int n_in,
                              void* d_out, int out_size)
{
    const float* q    = (const float*)d_in[0];
    const float* k    = (const float*)d_in[1];
    const float* v    = (const float*)d_in[2];
    const int*   mask = (const int*)d_in[3];
    const float* Wq   = (const float*)d_in[4];
    const float* bq   = (const float*)d_in[5];
    const float* Wk   = (const float*)d_in[6];
    const float* bk   = (const float*)d_in[7];
    const float* Wv   = (const float*)d_in[8];
    const float* bv   = (const float*)d_in[9];
    const float* Wfc  = (const float*)d_in[10];
    const float* bfc  = (const float*)d_in[11];

    float* out = (float*)d_out;                      // [B, L, D]
    float* att = out + (size_t)B * L * D;            // [B, H, L, L]

    __half *Qh = nullptr, *Kh = nullptr, *Vt = nullptr;
    cudaGetSymbolAddress((void**)&Qh, g_Qh);
    cudaGetSymbolAddress((void**)&Kh, g_Kh);
    cudaGetSymbolAddress((void**)&Vt, g_Vt);

    const int smem_gemm  = 4 * 9216 * 2;                       // 73728
    const int smem_stats = 3 * 9216 * 2 + 128 * 4 * 4;         // 57344
    const int smem_pv    = (4 * 4608 + 9216) * 2;              // 55296
    cudaFuncSetAttribute(gemm_proj_all, cudaFuncAttributeMaxDynamicSharedMemorySize, smem_gemm);
    cudaFuncSetAttribute(gemm_fc,       cudaFuncAttributeMaxDynamicSharedMemorySize, smem_gemm);
    cudaFuncSetAttribute(attn_stats,    cudaFuncAttributeMaxDynamicSharedMemorySize, smem_stats);
    cudaFuncSetAttribute(attn_pv,       cudaFuncAttributeMaxDynamicSharedMemorySize, smem_pv);

    // ---- capture-legal fork: side streams join via root event --------------
    cudaEventRecord(g_ov.evRoot, 0);
    cudaStreamWaitEvent(g_ov.s1, g_ov.evRoot, 0);
    cudaStreamWaitEvent(g_ov.s2, g_ov.evRoot, 0);

    transposeW<<<dim3(32, 32, 4), 256, 0, g_ov.s1>>>(Wq, Wk, Wv, Wfc);
    cudaEventRecord(g_ov.evT, g_ov.s1);
    packmask<<<(int)((size_t)B * L * L / 256), 256, 0, g_ov.s2>>>(mask);
    cudaEventRecord(g_ov.evM, g_ov.s2);
    preround<<<(int)(3 * NX / 4 / 256), 256>>>(
        (const float4*)q, (const float4*)k, (const float4*)v);
    cudaEventRecord(g_ov.evPre, 0);

    // ---- projections: QK on s0; V forked to s1 (overlaps with stats) -------
    cudaStreamWaitEvent(0, g_ov.evT, 0);
    dim3 gqk(D / 128, ML / 128, 2);   // z = 0,1
    gemm_proj_all<<<gqk, 128, smem_gemm>>>(bq, bk, bv, Qh, Kh, Vt, 0);

    cudaStreamWaitEvent(g_ov.s1, g_ov.evPre, 0);
    dim3 gv(D / 128, ML / 128, 1);    // z = 2
    gemm_proj_all<<<gv, 128, smem_gemm, g_ov.s1>>>(bq, bk, bv, Qh, Kh, Vt, 2);
    cudaEventRecord(g_ov.evV, g_ov.s1);

    // ---- attention ----------------------------------------------------------
    cudaStreamWaitEvent(0, g_ov.evM, 0);
    dim3 ga(L / 128, BH);             // (16, 64)
    attn_stats<<<ga, 256, smem_stats>>>();

    cudaStreamWaitEvent(0, g_ov.evV, 0);
    attn_pv<<<ga, 256, smem_pv>>>(att);

    // ---- output projection --------------------------------------------------
    dim3 gf(D / 128, ML / 128);       // (8, 64)
    gemm_fc<<<gf, 128, smem_gemm>>>(q, bfc, out);
}

// round 15
// speedup vs baseline: 1.0184x; 1.0184x over previous
#include <cuda_runtime.h>
#include <cuda_fp16.h>
#include <cstdint>

namespace {
constexpr int B = 4, L = 2048, D = 1024, H = 16, DH = 64;
constexpr int BH = B * H;    // 64
constexpr int ML = B * L;    // 8192
constexpr float LOG2E = 1.4426950408889634f;
constexpr size_t NX = (size_t)ML * D;        // elems per q/k/v
constexpr size_t NW = (size_t)D * D;         // elems per W
constexpr int MW = L / 32;                   // mask words per row
constexpr int ST = 72;                       // smem row stride (halves) = 144 B
}

__device__ __half g_Qh[(size_t)B * H * L * DH];   // [bh, l, d]
__device__ __half g_Kh[(size_t)B * H * L * DH];   // [bh, l, d]
__device__ __half g_Vt[(size_t)B * H * DH * L];   // [bh, d, l] (transposed)
__device__ __half g_OutH[(size_t)B * L * H * DH]; // [b*L, h*64]
__device__ float2 g_stats[(size_t)BH * L];        // per row: (m_off, inv)
__device__ __half g_xR[3 * NX];                   // fp16 q|k|v
__device__ __half g_WT[4 * NW];                   // W^T fp16: [n][k]
__device__ uint32_t g_mbits[(size_t)B * L * MW];  // packed mask bits

// ---------------------------------------------------------------------------
// streams/events for capture-legal fork-join overlap (static init)
// ---------------------------------------------------------------------------
namespace {
struct OverlapRes {
    cudaStream_t s1, s2;
    cudaEvent_t evRoot, evPre, evT, evM, evV;
    OverlapRes() {
        cudaStreamCreateWithFlags(&s1, cudaStreamNonBlocking);
        cudaStreamCreateWithFlags(&s2, cudaStreamNonBlocking);
        cudaEventCreateWithFlags(&evRoot, cudaEventDisableTiming);
        cudaEventCreateWithFlags(&evPre,  cudaEventDisableTiming);
        cudaEventCreateWithFlags(&evT,    cudaEventDisableTiming);
        cudaEventCreateWithFlags(&evM,    cudaEventDisableTiming);
        cudaEventCreateWithFlags(&evV,    cudaEventDisableTiming);
    }
};
OverlapRes g_ov;
}

// ---------------------------------------------------------------------------
// helpers
// ---------------------------------------------------------------------------
__device__ __forceinline__ void mma16(float* c, const uint32_t* a, const uint32_t* b) {
    asm("mma.sync.aligned.m16n8k16.row.col.f32.f16.f16.f32 "
        "{%0,%1,%2,%3},{%4,%5,%6,%7},{%8,%9},{%0,%1,%2,%3};"
        : "+f"(c[0]), "+f"(c[1]), "+f"(c[2]), "+f"(c[3])
        : "r"(a[0]), "r"(a[1]), "r"(a[2]), "r"(a[3]), "r"(b[0]), "r"(b[1]));
}
__device__ __forceinline__ void ldsm4(uint32_t* r, uint32_t addr) {
    asm volatile("ldmatrix.sync.aligned.m8n8.x4.shared.b16 {%0,%1,%2,%3}, [%4];"
                 : "=r"(r[0]), "=r"(r[1]), "=r"(r[2]), "=r"(r[3]) : "r"(addr));
}
__device__ __forceinline__ uint32_t smaddr(const void* p) {
    return (uint32_t)__cvta_generic_to_shared(p);
}
__device__ __forceinline__ void cpa16(uint32_t dst, const void* src) {
    asm volatile("cp.async.ca.shared.global [%0], [%1], 16;\n" :: "r"(dst), "l"(src));
}
__device__ __forceinline__ void cp_commit() {
    asm volatile("cp.async.commit_group;\n");
}
template <int N> __device__ __forceinline__ void cp_wait() {
    asm volatile("cp.async.wait_group %0;\n" :: "n"(N));
}
__device__ __forceinline__ void st_cs_f2(float* p, float x, float y) {
    asm volatile("st.global.cs.v2.f32 [%0], {%1, %2};"
                 :: "l"(p), "f"(x), "f"(y) : "memory");
}

// ---------------------------------------------------------------------------
// Pre-convert q/k/v to fp16 (rne), once.
// ---------------------------------------------------------------------------
__global__ __launch_bounds__(256) void preround(
    const float4* __restrict__ q, const float4* __restrict__ k,
    const float4* __restrict__ v)
{
    const size_t NX4 = NX / 4;
    size_t i = (size_t)blockIdx.x * 256 + threadIdx.x;
    const float4* src = (i < NX4) ? q : (i < 2 * NX4) ? k : v;
    size_t off = (i < NX4) ? i : (i < 2 * NX4) ? i - NX4 : i - 2 * NX4;
    float4 x = src[off];
    ((__half2*)g_xR)[2 * i]     = __floats2half2_rn(x.x, x.y);
    ((__half2*)g_xR)[2 * i + 1] = __floats2half2_rn(x.z, x.w);
}

// ---------------------------------------------------------------------------
// Transpose + convert weights: g_WT[z][n][k] = fp16(W_z[k][n]).
// ---------------------------------------------------------------------------
__global__ __launch_bounds__(256) void transposeW(
    const float* __restrict__ wq, const float* __restrict__ wk,
    const float* __restrict__ wv, const float* __restrict__ wfc)
{
    __shared__ float t[32][33];
    const int z = blockIdx.z;
    const float* src = (z == 0) ? wq : (z == 1) ? wk : (z == 2) ? wv : wfc;
    const int k0 = blockIdx.y * 32, n0 = blockIdx.x * 32;
    const int x = threadIdx.x & 31, y = threadIdx.x >> 5;  // 32 x 8
#pragma unroll
    for (int j = 0; j < 4; j++)
        t[y + j * 8][x] = src[(size_t)(k0 + y + j * 8) * D + n0 + x];
    __syncthreads();
#pragma unroll
    for (int j = 0; j < 4; j++)
        g_WT[(size_t)z * NW + (size_t)(n0 + y + j * 8) * D + k0 + x] =
            __float2half_rn(t[x][y + j * 8]);
}

// ---------------------------------------------------------------------------
// Pack int32 mask -> bitmask.
// ---------------------------------------------------------------------------
__global__ __launch_bounds__(256) void packmask(const int* __restrict__ mask)
{
    size_t i = (size_t)blockIdx.x * 256 + threadIdx.x;
    int mv = mask[i];
    uint32_t bal = __ballot_sync(0xffffffffu, mv != 0);
    if ((threadIdx.x & 31) == 0) g_mbits[i >> 5] = bal;
}

// ---------------------------------------------------------------------------
// GEMM 1: QKV projections (z = blockIdx.z + zbase).  fp16 mma m16n8k16.
// 128 thr, 4 warps, warp tile 64x64, ktile 64, cp.async 3-STAGE.
// V stored TRANSPOSED [bh, d, l].
// ---------------------------------------------------------------------------
__global__ __launch_bounds__(128, 2) void gemm_proj_all(
    const float* __restrict__ bq, const float* __restrict__ bk,
    const float* __restrict__ bv,
    __half* __restrict__ Qh, __half* __restrict__ Kh, __half* __restrict__ Vt,
    int zbase)
{
    const int z = blockIdx.z + zbase;
    const __half* X = g_xR + (size_t)z * NX;
    const __half* WT = g_WT + (size_t)z * NW;
    const float* bias = (z == 0) ? bq : (z == 1) ? bk : bv;
    const float scale = (z == 0) ? 0.125f : 1.0f;

    extern __shared__ __half dynh[];
    __half* As = dynh;                  // 3 x [128][72]
    __half* Bs = dynh + 3 * 9216;       // 3 x [128][72]

    const int tid = threadIdx.x;
    const int lane = tid & 31, w = tid >> 5;
    const int g = lane >> 2, tg = lane & 3;
    const int wm = (w >> 1) * 64, wn = (w & 1) * 64;
    const int m0 = blockIdx.y * 128, n0 = blockIdx.x * 128;

    const uint32_t a_base0 = smaddr(As) +
        (((wm + (lane & 15)) * ST + (lane >> 4) * 8) << 1);
    const uint32_t b_base0 = smaddr(Bs) +
        (((wn + (lane & 15)) * ST + (lane >> 4) * 8) << 1);

    auto issue = [&](int s, int k0) {
#pragma unroll
        for (int t = 0; t < 8; t++) {           // A: 128x64 halves = 16 KB
            int idx = tid + t * 128;
            int row = idx >> 3, cc = (idx & 7) * 8;
            cpa16(smaddr(As + s * 9216 + row * ST + cc),
                  X + (size_t)(m0 + row) * D + k0 + cc);
        }
#pragma unroll
        for (int t = 0; t < 8; t++) {           // B: 128x64 halves
            int idx = tid + t * 128;
            int row = idx >> 3, cc = (idx & 7) * 8;
            cpa16(smaddr(Bs + s * 9216 + row * ST + cc),
                  WT + (size_t)(n0 + row) * D + k0 + cc);
        }
    };

    float c[4][8][4];
#pragma unroll
    for (int mi = 0; mi < 4; mi++)
#pragma unroll
        for (int ni = 0; ni < 8; ni++)
#pragma unroll
            for (int r = 0; r < 4; r++) c[mi][ni][r] = 0.f;

    issue(0, 0);  cp_commit();
    issue(1, 64); cp_commit();

    for (int t = 0; t < 16; t++) {
        if (t + 2 < 16) { issue((t + 2) % 3, (t + 2) * 64); cp_commit(); cp_wait<2>(); }
        else if (t + 1 < 16) cp_wait<1>();
        else cp_wait<0>();
        __syncthreads();
        const int sb = t % 3;
        const uint32_t aB = a_base0 + sb * 9216 * 2;
        const uint32_t bB = b_base0 + sb * 9216 * 2;
#pragma unroll
        for (int ks = 0; ks < 4; ks++) {
            const int kk = ks * 16;
            uint32_t a[4][4], bb[8][2];
#pragma unroll
            for (int mi = 0; mi < 4; mi++)
                ldsm4(a[mi], aB + ((mi * 16 * ST + kk) << 1));
#pragma unroll
            for (int pr = 0; pr < 4; pr++) {
                uint32_t rr[4];
                ldsm4(rr, bB + ((pr * 16 * ST + kk) << 1));
                bb[2 * pr][0] = rr[0]; bb[2 * pr][1] = rr[2];
                bb[2 * pr + 1][0] = rr[1]; bb[2 * pr + 1][1] = rr[3];
            }
#pragma unroll
            for (int mi = 0; mi < 4; mi++)
#pragma unroll
                for (int ni = 0; ni < 8; ni++)
                    mma16(c[mi][ni], a[mi], bb[ni]);
        }
        __syncthreads();
    }
    const int bblk = m0 / L, lbase = m0 % L;
    if (z < 2) {
        __half* OutHeads = (z == 0) ? Qh : Kh;
#pragma unroll
        for (int mi = 0; mi < 4; mi++)
#pragma unroll
            for (int r = 0; r < 2; r++) {
                int l = lbase + wm + mi * 16 + g + r * 8;
#pragma unroll
                for (int ni = 0; ni < 8; ni++) {
                    int n = n0 + wn + ni * 8 + tg * 2;
                    int h = n >> 6, d = n & 63;
                    *(__half2*)&OutHeads[(((size_t)bblk * H + h) * L + l) * DH + d] =
                        __floats2half2_rn((c[mi][ni][r * 2 + 0] + bias[n]) * scale,
                                          (c[mi][ni][r * 2 + 1] + bias[n + 1]) * scale);
                }
            }
    } else {
#pragma unroll
        for (int mi = 0; mi < 4; mi++)
#pragma unroll
            for (int r = 0; r < 2; r++) {
                int l = lbase + wm + mi * 16 + g + r * 8;
#pragma unroll
                for (int ni = 0; ni < 8; ni++) {
                    int n = n0 + wn + ni * 8 + tg * 2;
                    int h = n >> 6, d = n & 63;
                    size_t base = ((size_t)(bblk * H + h) * DH + d) * L + l;
                    Vt[base]     = __float2half_rn(c[mi][ni][r * 2 + 0] + bias[n]);
                    Vt[base + L] = __float2half_rn(c[mi][ni][r * 2 + 1] + bias[n + 1]);
                }
            }
    }
}

// ---------------------------------------------------------------------------
// Pass 1: per-row expsum (no max pass; scores bounded).  fp16 mma, fp32 exp.
// ---------------------------------------------------------------------------
__global__ __launch_bounds__(256, 2) void attn_stats()
{
    extern __shared__ __half dynh[];
    __half* Qs = dynh;                        // [128][72]
    __half* Ks = dynh + 9216;                 // 2 x [128][72]
    float* red = (float*)(dynh + 3 * 9216);   // [128][4]

    const int tid = threadIdx.x;
    const int lane = tid & 31, w = tid >> 5;
    const int g = lane >> 2, tg = lane & 3;
    const int wm = (w >> 2) * 64, wn = (w & 3) * 32;
    const int bh = blockIdx.y, b = bh >> 4;
    const int i0 = blockIdx.x * 128;
    const __half* Qb = g_Qh + (size_t)bh * L * DH;
    const __half* Kb = g_Kh + (size_t)bh * L * DH;
    const uint32_t* mb = g_mbits + (size_t)b * L * MW;

    const uint32_t q_base = smaddr(Qs) +
        (((wm + (lane & 15)) * ST + (lane >> 4) * 8) << 1);
    const uint32_t k_base0 = smaddr(Ks) +
        (((wn + (lane & 15)) * ST + (lane >> 4) * 8) << 1);

    auto issueK = [&](int s, int j0) {
#pragma unroll
        for (int t = 0; t < 4; t++) {
            int idx = tid + t * 256;
            int row = idx >> 3, cc = (idx & 7) * 8;
            cpa16(smaddr(Ks + s * 9216 + row * ST + cc),
                  Kb + (size_t)(j0 + row) * DH + cc);
        }
    };
#pragma unroll
    for (int t = 0; t < 4; t++) {
        int idx = tid + t * 256;
        int row = idx >> 3, cc = (idx & 7) * 8;
        cpa16(smaddr(Qs + row * ST + cc), Qb + (size_t)(i0 + row) * DH + cc);
    }
    issueK(0, 0); cp_commit();

    float l_run[4][2];
#pragma unroll
    for (int mi = 0; mi < 4; mi++)
#pragma unroll
        for (int r = 0; r < 2; r++) l_run[mi][r] = 0.f;

    for (int jt = 0; jt < 16; jt++) {
        const int j0 = jt * 128;
        if (jt + 1 < 16) { issueK((jt + 1) & 1, (jt + 1) * 128); cp_commit(); cp_wait<1>(); }
        else cp_wait<0>();
        __syncthreads();
        const uint32_t kB = k_base0 + (jt & 1) * 9216 * 2;

        float c[4][4][4];
#pragma unroll
        for (int mi = 0; mi < 4; mi++)
#pragma unroll
            for (int ni = 0; ni < 4; ni++)
#pragma unroll
                for (int r = 0; r < 4; r++) c[mi][ni][r] = 0.f;
#pragma unroll
        for (int ks = 0; ks < 4; ks++) {
            const int kk = ks * 16;
            uint32_t a[4][4], bb[4][2];
#pragma unroll
            for (int mi = 0; mi < 4; mi++)
                ldsm4(a[mi], q_base + ((mi * 16 * ST + kk) << 1));
#pragma unroll
            for (int pr = 0; pr < 2; pr++) {
                uint32_t rr[4];
                ldsm4(rr, kB + ((pr * 16 * ST + kk) << 1));
                bb[2 * pr][0] = rr[0]; bb[2 * pr][1] = rr[2];
                bb[2 * pr + 1][0] = rr[1]; bb[2 * pr + 1][1] = rr[3];
            }
#pragma unroll
            for (int mi = 0; mi < 4; mi++)
#pragma unroll
                for (int ni = 0; ni < 4; ni++)
                    mma16(c[mi][ni], a[mi], bb[ni]);
        }

#pragma unroll
        for (int mi = 0; mi < 4; mi++)
#pragma unroll
            for (int r = 0; r < 2; r++) {
                int i = i0 + wm + mi * 16 + g + r * 8;
                uint32_t word = mb[(size_t)i * MW + ((j0 + wn) >> 5)];
                float acc = 0.f;
#pragma unroll
                for (int ni = 0; ni < 4; ni++) {
                    int bit = ni * 8 + tg * 2;
                    float e0 = exp2f(c[mi][ni][r * 2 + 0] * LOG2E);
                    float e1 = exp2f(c[mi][ni][r * 2 + 1] * LOG2E);
                    acc += (word >> bit) & 1 ? e0 : 0.f;
                    acc += (word >> (bit + 1)) & 1 ? e1 : 0.f;
                }
                l_run[mi][r] += acc;
            }
        __syncthreads();
    }
#pragma unroll
    for (int mi = 0; mi < 4; mi++)
#pragma unroll
        for (int r = 0; r < 2; r++) {
            float l = l_run[mi][r];
            l += __shfl_xor_sync(0xffffffffu, l, 1);
            l += __shfl_xor_sync(0xffffffffu, l, 2);
            if ((lane & 3) == 0)
                red[(wm + mi * 16 + g + r * 8) * 4 + (w & 3)] = l;
        }
    __syncthreads();
    if (tid < 128) {
        float l = red[tid * 4 + 0] + red[tid * 4 + 1]
                + red[tid * 4 + 2] + red[tid * 4 + 3];
        g_stats[(size_t)bh * L + i0 + tid] =
            (l == 0.f) ? make_float2(-1e9f, 1.f / (float)L)
                       : make_float2(0.f, 1.f / l);
    }
}

// ---------------------------------------------------------------------------
// Pass 2: recompute scores, normalize, write att once (.cs), O = P@V.
// fp16 mma; fp32 exp; now 2 CTAs/SM.
// ---------------------------------------------------------------------------
__global__ __launch_bounds__(256, 2) void attn_pv(float* __restrict__ att)
{
    extern __shared__ __half dynh[];
    __half* Ks = dynh;                    // 2 x [64][72] = 2 x 4608
    __half* Vs = dynh + 2 * 4608;         // 2 x [64][72]
    __half* Ps = dynh + 4 * 4608;         // [128][72]

    const int tid = threadIdx.x;
    const int lane = tid & 31, w = tid >> 5;
    const int g = lane >> 2, tg = lane & 3;
    const int rg = w >> 1;                 // rows rg*32..+32
    const int jg = w & 1;                  // scores j half
    const int dg = w & 1;                  // PV d half
    const int bh = blockIdx.y, b = bh >> 4, h = bh & 15;
    const int i0 = blockIdx.x * 128;
    const __half* Qb = g_Qh + (size_t)bh * L * DH;
    const __half* Kb = g_Kh + (size_t)bh * L * DH;
    const __half* Vb = g_Vt + (size_t)bh * DH * L;
    const uint32_t* mb = g_mbits + (size_t)b * L * MW;
    float* arow = att + (size_t)bh * L * L;

    // stage Q (128x64) into Ps
#pragma unroll
    for (int t = 0; t < 4; t++) {
        int idx = tid + t * 256;
        int row = idx >> 3, cc = (idx & 7) * 8;
        cpa16(smaddr(Ps + row * ST + cc), Qb + (size_t)(i0 + row) * DH + cc);
    }
    cp_commit();

    auto issueKV = [&](int s, int j0) {
#pragma unroll
        for (int t = 0; t < 2; t++) {           // K: 64x64 halves
            int idx = tid + t * 256;
            int row = idx >> 3, cc = (idx & 7) * 8;
            cpa16(smaddr(Ks + s * 4608 + row * ST + cc),
                  Kb + (size_t)(j0 + row) * DH + cc);
        }
#pragma unroll
        for (int t = 0; t < 2; t++) {           // V: 64 d-rows x 64 j
            int idx = tid + t * 256;
            int row = idx >> 3, cc = (idx & 7) * 8;
            cpa16(smaddr(Vs + s * 4608 + row * ST + cc),
                  Vb + (size_t)row * L + j0 + cc);
        }
    };
    issueKV(0, 0); cp_commit();

    cp_wait<1>();
    __syncthreads();

    uint32_t qf[2][4][4];
    {
        const uint32_t qb = smaddr(Ps) +
            (((rg * 32 + (lane & 15)) * ST + (lane >> 4) * 8) << 1);
#pragma unroll
        for (int mi = 0; mi < 2; mi++)
#pragma unroll
            for (int ks = 0; ks < 4; ks++)
                ldsm4(qf[mi][ks], qb + ((mi * 16 * ST + ks * 16) << 1));
    }

    float sm[2][2], sinv[2][2];
#pragma unroll
    for (int mi = 0; mi < 2; mi++)
#pragma unroll
        for (int r = 0; r < 2; r++) {
            float2 s = g_stats[(size_t)bh * L + i0 + rg * 32 + mi * 16 + g + r * 8];
            sm[mi][r] = s.x; sinv[mi][r] = s.y;
        }

    const uint32_t k_base0 = smaddr(Ks) +
        (((jg * 32 + (lane & 15)) * ST + (lane >> 4) * 8) << 1);
    const uint32_t v_base0 = smaddr(Vs) +
        (((dg * 32 + (lane & 15)) * ST + (lane >> 4) * 8) << 1);
    const uint32_t p_base = smaddr(Ps) +
        (((rg * 32 + (lane & 15)) * ST + (lane >> 4) * 8) << 1);

    float co[2][4][4];
#pragma unroll
    for (int mi = 0; mi < 2; mi++)
#pragma unroll
        for (int ni = 0; ni < 4; ni++)
#pragma unroll
            for (int r = 0; r < 4; r++) co[mi][ni][r] = 0.f;

    for (int ch = 0; ch < 32; ch++) {
        if (ch + 1 < 32) { issueKV((ch + 1) & 1, (ch + 1) * 64); cp_commit(); cp_wait<1>(); }
        else cp_wait<0>();
        __syncthreads();
        const uint32_t kB = k_base0 + (ch & 1) * 4608 * 2;
        const uint32_t vB = v_base0 + (ch & 1) * 4608 * 2;

        // scores: 32 rows x 32 j (jg half), k = 64
        float c2[2][4][4];
#pragma unroll
        for (int mi = 0; mi < 2; mi++)
#pragma unroll
            for (int ni = 0; ni < 4; ni++)
#pragma unroll
                for (int r = 0; r < 4; r++) c2[mi][ni][r] = 0.f;
#pragma unroll
        for (int ks = 0; ks < 4; ks++) {
            uint32_t bb[4][2];
#pragma unroll
            for (int pr = 0; pr < 2; pr++) {
                uint32_t rr[4];
                ldsm4(rr, kB + ((pr * 16 * ST + ks * 16) << 1));
                bb[2 * pr][0] = rr[0]; bb[2 * pr][1] = rr[2];
                bb[2 * pr + 1][0] = rr[1]; bb[2 * pr + 1][1] = rr[3];
            }
#pragma unroll
            for (int mi = 0; mi < 2; mi++)
#pragma unroll
                for (int ni = 0; ni < 4; ni++)
                    mma16(c2[mi][ni], qf[mi][ks], bb[ni]);
        }

        // mask + exp + normalize; write att (.cs); stage P (fp16)
        const int j0 = ch * 64;
#pragma unroll
        for (int mi = 0; mi < 2; mi++)
#pragma unroll
            for (int r = 0; r < 2; r++) {
                int rl = rg * 32 + mi * 16 + g + r * 8;
                int i = i0 + rl;
                uint32_t word = mb[(size_t)i * MW + ((j0 + jg * 32) >> 5)];
                float m = sm[mi][r], inv = sinv[mi][r];
#pragma unroll
                for (int ni = 0; ni < 4; ni++) {
                    int bit = ni * 8 + tg * 2;
                    int cl = jg * 32 + bit;
                    float s0 = (word >> bit) & 1 ? c2[mi][ni][r * 2 + 0] : -1e9f;
                    float s1 = (word >> (bit + 1)) & 1 ? c2[mi][ni][r * 2 + 1] : -1e9f;
                    float p0 = exp2f((s0 - m) * LOG2E) * inv;
                    float p1 = exp2f((s1 - m) * LOG2E) * inv;
                    st_cs_f2(arow + (size_t)i * L + j0 + cl, p0, p1);
                    *(__half2*)&Ps[rl * ST + cl] = __floats2half2_rn(p0, p1);
                }
            }
        asm volatile("bar.sync %0, %1;" :: "r"(rg + 1), "r"(64) : "memory");

        // PV: 32 rows x 32 d (dg half), k = 64 (j)
#pragma unroll
        for (int ks = 0; ks < 4; ks++) {
            uint32_t a[2][4], bb[4][2];
#pragma unroll
            for (int mi = 0; mi < 2; mi++)
                ldsm4(a[mi], p_base + ((mi * 16 * ST + ks * 16) << 1));
#pragma unroll
            for (int pr = 0; pr < 2; pr++) {
                uint32_t rr[4];
                ldsm4(rr, vB + ((pr * 16 * ST + ks * 16) << 1));
                bb[2 * pr][0] = rr[0]; bb[2 * pr][1] = rr[2];
                bb[2 * pr + 1][0] = rr[1]; bb[2 * pr + 1][1] = rr[3];
            }
#pragma unroll
            for (int mi = 0; mi < 2; mi++)
#pragma unroll
                for (int ni = 0; ni < 4; ni++)
                    mma16(co[mi][ni], a[mi], bb[ni]);
        }
        __syncthreads();
    }
#pragma unroll
    for (int mi = 0; mi < 2; mi++)
#pragma unroll
        for (int ni = 0; ni < 4; ni++) {
            int d = dg * 32 + ni * 8 + tg * 2;
            int row0 = i0 + rg * 32 + mi * 16 + g;
            *(__half2*)&g_OutH[(size_t)(b * L + row0) * D + h * DH + d] =
                __floats2half2_rn(co[mi][ni][0], co[mi][ni][1]);
            *(__half2*)&g_OutH[(size_t)(b * L + row0 + 8) * D + h * DH + d] =
                __floats2half2_rn(co[mi][ni][2], co[mi][ni][3]);
        }
}

// ---------------------------------------------------------------------------
// GEMM 4: out = OutH @ Wfc + bfc + q.  fp16, 3-stage, same structure as proj.
// ---------------------------------------------------------------------------
__global__ __launch_bounds__(128, 2) void gemm_fc(
    const float* __restrict__ Xres,
    const float* __restrict__ bias, float* __restrict__ Out)
{
    extern __shared__ __half dynh[];
    __half* As = dynh;
    __half* Bs = dynh + 3 * 9216;
    const __half* WT = g_WT + 3 * NW;

    const int tid = threadIdx.x;
    const int lane = tid & 31, w = tid >> 5;
    const int g = lane >> 2, tg = lane & 3;
    const int wm = (w >> 1) * 64, wn = (w & 1) * 64;
    const int m0 = blockIdx.y * 128, n0 = blockIdx.x * 128;

    const uint32_t a_base0 = smaddr(As) +
        (((wm + (lane & 15)) * ST + (lane >> 4) * 8) << 1);
    const uint32_t b_base0 = smaddr(Bs) +
        (((wn + (lane & 15)) * ST + (lane >> 4) * 8) << 1);

    auto issue = [&](int s, int k0) {
#pragma unroll
        for (int t = 0; t < 8; t++) {
            int idx = tid + t * 128;
            int row = idx >> 3, cc = (idx & 7) * 8;
            cpa16(smaddr(As + s * 9216 + row * ST + cc),
                  g_OutH + (size_t)(m0 + row) * D + k0 + cc);
        }
#pragma unroll
        for (int t = 0; t < 8; t++) {
            int idx = tid + t * 128;
            int row = idx >> 3, cc = (idx & 7) * 8;
            cpa16(smaddr(Bs + s * 9216 + row * ST + cc),
                  WT + (size_t)(n0 + row) * D + k0 + cc);
        }
    };

    float c[4][8][4];
#pragma unroll
    for (int mi = 0; mi < 4; mi++)
#pragma unroll
        for (int ni = 0; ni < 8; ni++)
#pragma unroll
            for (int r = 0; r < 4; r++) c[mi][ni][r] = 0.f;

    issue(0, 0);  cp_commit();
    issue(1, 64); cp_commit();

    for (int t = 0; t < 16; t++) {
        if (t + 2 < 16) { issue((t + 2) % 3, (t + 2) * 64); cp_commit(); cp_wait<2>(); }
        else if (t + 1 < 16) cp_wait<1>();
        else cp_wait<0>();
        __syncthreads();
        const int sb = t % 3;
        const uint32_t aB = a_base0 + sb * 9216 * 2;
        const uint32_t bB = b_base0 + sb * 9216 * 2;
#pragma unroll
        for (int ks = 0; ks < 4; ks++) {
            const int kk = ks * 16;
            uint32_t a[4][4], bb[8][2];
#pragma unroll
            for (int mi = 0; mi < 4; mi++)
                ldsm4(a[mi], aB + ((mi * 16 * ST + kk) << 1));
#pragma unroll
            for (int pr = 0; pr < 4; pr++) {
                uint32_t rr[4];
                ldsm4(rr, bB + ((pr * 16 * ST + kk) << 1));
                bb[2 * pr][0] = rr[0]; bb[2 * pr][1] = rr[2];
                bb[2 * pr + 1][0] = rr[1]; bb[2 * pr + 1][1] = rr[3];
            }
#pragma unroll
            for (int mi = 0; mi < 4; mi++)
#pragma unroll
                for (int ni = 0; ni < 8; ni++)
                    mma16(c[mi][ni], a[mi], bb[ni]);
        }
        __syncthreads();
    }
#pragma unroll
    for (int mi = 0; mi < 4; mi++)
#pragma unroll
        for (int r = 0; r < 2; r++) {
            int gm = m0 + wm + mi * 16 + g + r * 8;
#pragma unroll
            for (int ni = 0; ni < 8; ni++) {
                int gn = n0 + wn + ni * 8 + tg * 2;
                float2 res = *(const float2*)(Xres + (size_t)gm * D + gn);
                float2 o;
                o.x = c[mi][ni][r * 2 + 0] + bias[gn]     + res.x;
                o.y = c[mi][ni][r * 2 + 1] + bias[gn + 1] + res.y;
                *(float2*)&Out[(size_t)gm * D + gn] = o;
            }
        }
}

// ---------------------------------------------------------------------------
extern "C" void kernel_launch(void* const* d_in, const int* in_sizes, int n_in,
                              void* d_out, int out_size)
{
    const float* q    = (const float*)d_in[0];
    const float* k    = (const float*)d_in[1];
    const float* v    = (const float*)d_in[2];
    const int*   mask = (const int*)d_in[3];
    const float* Wq   = (const float*)d_in[4];
    const float* bq   = (const float*)d_in[5];
    const float* Wk   = (const float*)d_in[6];
    const float* bk   = (const float*)d_in[7];
    const float* Wv   = (const float*)d_in[8];
    const float* bv   = (const float*)d_in[9];
    const float* Wfc  = (const float*)d_in[10];
    const float* bfc  = (const float*)d_in[11];

    float* out = (float*)d_out;                      // [B, L, D]
    float* att = out + (size_t)B * L * D;            // [B, H, L, L]

    __half *Qh = nullptr, *Kh = nullptr, *Vt = nullptr;
    cudaGetSymbolAddress((void**)&Qh, g_Qh);
    cudaGetSymbolAddress((void**)&Kh, g_Kh);
    cudaGetSymbolAddress((void**)&Vt, g_Vt);

    const int smem_gemm  = 6 * 9216 * 2;                       // 110592
    const int smem_stats = 3 * 9216 * 2 + 128 * 4 * 4;         // 57344
    const int smem_pv    = (4 * 4608 + 9216) * 2;              // 55296
    cudaFuncSetAttribute(gemm_proj_all, cudaFuncAttributeMaxDynamicSharedMemorySize, smem_gemm);
    cudaFuncSetAttribute(gemm_fc,       cudaFuncAttributeMaxDynamicSharedMemorySize, smem_gemm);
    cudaFuncSetAttribute(attn_stats,    cudaFuncAttributeMaxDynamicSharedMemorySize, smem_stats);
    cudaFuncSetAttribute(attn_pv,       cudaFuncAttributeMaxDynamicSharedMemorySize, smem_pv);

    // ---- capture-legal fork: side streams join via root event --------------
    cudaEventRecord(g_ov.evRoot, 0);
    cudaStreamWaitEvent(g_ov.s1, g_ov.evRoot, 0);
    cudaStreamWaitEvent(g_ov.s2, g_ov.evRoot, 0);

    transposeW<<<dim3(32, 32, 4), 256, 0, g_ov.s1>>>(Wq, Wk, Wv, Wfc);
    cudaEventRecord(g_ov.evT, g_ov.s1);
    packmask<<<(int)((size_t)B * L * L / 256), 256, 0, g_ov.s2>>>(mask);
    cudaEventRecord(g_ov.evM, g_ov.s2);
    preround<<<(int)(3 * NX / 4 / 256), 256>>>(
        (const float4*)q, (const float4*)k, (const float4*)v);
    cudaEventRecord(g_ov.evPre, 0);

    // ---- projections: QK on s0; V forked to s1 (overlaps with stats) -------
    cudaStreamWaitEvent(0, g_ov.evT, 0);
    dim3 gqk(D / 128, ML / 128, 2);   // z = 0,1
    gemm_proj_all<<<gqk, 128, smem_gemm>>>(bq, bk, bv, Qh, Kh, Vt, 0);

    cudaStreamWaitEvent(g_ov.s1, g_ov.evPre, 0);
    dim3 gv(D / 128, ML / 128, 1);    // z = 2
    gemm_proj_all<<<gv, 128, smem_gemm, g_ov.s1>>>(bq, bk, bv, Qh, Kh, Vt, 2);
    cudaEventRecord(g_ov.evV, g_ov.s1);

    // ---- attention ----------------------------------------------------------
    cudaStreamWaitEvent(0, g_ov.evM, 0);
    dim3 ga(L / 128, BH);             // (16, 64)
    attn_stats<<<ga, 256, smem_stats>>>();

    cudaStreamWaitEvent(0, g_ov.evV, 0);
    attn_pv<<<ga, 256, smem_pv>>>(att);

    // ---- output projection --------------------------------------------------
    dim3 gf(D / 128, ML / 128);       // (8, 64)
    gemm_fc<<<gf, 128, smem_gemm>>>(q, bfc, out);
}

// round 16
// speedup vs baseline: 1.1131x; 1.0930x over previous
#include <cuda_runtime.h>
#include <cuda_fp16.h>
#include <cstdint>

namespace {
constexpr int B = 4, L = 2048, D = 1024, H = 16, DH = 64;
constexpr int BH = B * H;    // 64
constexpr int ML = B * L;    // 8192
constexpr float LOG2E = 1.4426950408889634f;
constexpr size_t NX = (size_t)ML * D;        // elems per q/k/v
constexpr size_t NW = (size_t)D * D;         // elems per W
constexpr int MW = L / 32;                   // mask words per row
constexpr int ST = 72;                       // smem row stride (halves) = 144 B
}

__device__ __half g_Qh[(size_t)B * H * L * DH];   // [bh, l, d]
__device__ __half g_Kh[(size_t)B * H * L * DH];   // [bh, l, d]
__device__ __half g_Vt[(size_t)B * H * DH * L];   // [bh, d, l] (transposed)
__device__ __half g_OutH[(size_t)B * L * H * DH]; // [b*L, h*64]
__device__ float2 g_stats[(size_t)BH * L];        // per row: (m_off, inv)
__device__ __half g_xR[3 * NX];                   // fp16 q|k|v
__device__ __half g_WT[4 * NW];                   // W^T fp16: [n][k]
__device__ uint32_t g_mbits[(size_t)B * L * MW];  // packed mask bits

// ---------------------------------------------------------------------------
// streams/events for capture-legal fork-join overlap (static init)
// ---------------------------------------------------------------------------
namespace {
struct OverlapRes {
    cudaStream_t s1, s2;
    cudaEvent_t evRoot, evPre, evT, evM, evV;
    OverlapRes() {
        cudaStreamCreateWithFlags(&s1, cudaStreamNonBlocking);
        cudaStreamCreateWithFlags(&s2, cudaStreamNonBlocking);
        cudaEventCreateWithFlags(&evRoot, cudaEventDisableTiming);
        cudaEventCreateWithFlags(&evPre,  cudaEventDisableTiming);
        cudaEventCreateWithFlags(&evT,    cudaEventDisableTiming);
        cudaEventCreateWithFlags(&evM,    cudaEventDisableTiming);
        cudaEventCreateWithFlags(&evV,    cudaEventDisableTiming);
    }
};
OverlapRes g_ov;
}

// ---------------------------------------------------------------------------
// helpers
// ---------------------------------------------------------------------------
__device__ __forceinline__ void mma16(float* c, const uint32_t* a, const uint32_t* b) {
    asm("mma.sync.aligned.m16n8k16.row.col.f32.f16.f16.f32 "
        "{%0,%1,%2,%3},{%4,%5,%6,%7},{%8,%9},{%0,%1,%2,%3};"
        : "+f"(c[0]), "+f"(c[1]), "+f"(c[2]), "+f"(c[3])
        : "r"(a[0]), "r"(a[1]), "r"(a[2]), "r"(a[3]), "r"(b[0]), "r"(b[1]));
}
__device__ __forceinline__ void ldsm4(uint32_t* r, uint32_t addr) {
    asm volatile("ldmatrix.sync.aligned.m8n8.x4.shared.b16 {%0,%1,%2,%3}, [%4];"
                 : "=r"(r[0]), "=r"(r[1]), "=r"(r[2]), "=r"(r[3]) : "r"(addr));
}
__device__ __forceinline__ uint32_t smaddr(const void* p) {
    return (uint32_t)__cvta_generic_to_shared(p);
}
__device__ __forceinline__ void cpa16(uint32_t dst, const void* src) {
    asm volatile("cp.async.ca.shared.global [%0], [%1], 16;\n" :: "r"(dst), "l"(src));
}
__device__ __forceinline__ void cp_commit() {
    asm volatile("cp.async.commit_group;\n");
}
template <int N> __device__ __forceinline__ void cp_wait() {
    asm volatile("cp.async.wait_group %0;\n" :: "n"(N));
}
__device__ __forceinline__ void st_cs_f2(float* p, float x, float y) {
    asm volatile("st.global.cs.v2.f32 [%0], {%1, %2};"
                 :: "l"(p), "f"(x), "f"(y) : "memory");
}

// ---------------------------------------------------------------------------
// Pre-convert q/k/v to fp16 (rne), once.
// ---------------------------------------------------------------------------
__global__ __launch_bounds__(256) void preround(
    const float4* __restrict__ q, const float4* __restrict__ k,
    const float4* __restrict__ v)
{
    const size_t NX4 = NX / 4;
    size_t i = (size_t)blockIdx.x * 256 + threadIdx.x;
    const float4* src = (i < NX4) ? q : (i < 2 * NX4) ? k : v;
    size_t off = (i < NX4) ? i : (i < 2 * NX4) ? i - NX4 : i - 2 * NX4;
    float4 x = src[off];
    ((__half2*)g_xR)[2 * i]     = __floats2half2_rn(x.x, x.y);
    ((__half2*)g_xR)[2 * i + 1] = __floats2half2_rn(x.z, x.w);
}

// ---------------------------------------------------------------------------
// Transpose + convert weights: g_WT[z][n][k] = fp16(W_z[k][n]).
// ---------------------------------------------------------------------------
__global__ __launch_bounds__(256) void transposeW(
    const float* __restrict__ wq, const float* __restrict__ wk,
    const float* __restrict__ wv, const float* __restrict__ wfc)
{
    __shared__ float t[32][33];
    const int z = blockIdx.z;
    const float* src = (z == 0) ? wq : (z == 1) ? wk : (z == 2) ? wv : wfc;
    const int k0 = blockIdx.y * 32, n0 = blockIdx.x * 32;
    const int x = threadIdx.x & 31, y = threadIdx.x >> 5;  // 32 x 8
#pragma unroll
    for (int j = 0; j < 4; j++)
        t[y + j * 8][x] = src[(size_t)(k0 + y + j * 8) * D + n0 + x];
    __syncthreads();
#pragma unroll
    for (int j = 0; j < 4; j++)
        g_WT[(size_t)z * NW + (size_t)(n0 + y + j * 8) * D + k0 + x] =
            __float2half_rn(t[x][y + j * 8]);
}

// ---------------------------------------------------------------------------
// Pack int32 mask -> bitmask.
// ---------------------------------------------------------------------------
__global__ __launch_bounds__(256) void packmask(const int* __restrict__ mask)
{
    size_t i = (size_t)blockIdx.x * 256 + threadIdx.x;
    int mv = mask[i];
    uint32_t bal = __ballot_sync(0xffffffffu, mv != 0);
    if ((threadIdx.x & 31) == 0) g_mbits[i >> 5] = bal;
}

// ---------------------------------------------------------------------------
// GEMM 1: QKV projections (z = blockIdx.z + zbase).  fp16 mma m16n8k16.
// 128 thr, 4 warps, warp tile 64x64, ktile 64, cp.async 2-stage.
// V stored TRANSPOSED [bh, d, l].
// ---------------------------------------------------------------------------
__global__ __launch_bounds__(128, 2) void gemm_proj_all(
    const float* __restrict__ bq, const float* __restrict__ bk,
    const float* __restrict__ bv,
    __half* __restrict__ Qh, __half* __restrict__ Kh, __half* __restrict__ Vt,
    int zbase)
{
    const int z = blockIdx.z + zbase;
    const __half* X = g_xR + (size_t)z * NX;
    const __half* WT = g_WT + (size_t)z * NW;
    const float* bias = (z == 0) ? bq : (z == 1) ? bk : bv;
    const float scale = (z == 0) ? 0.125f : 1.0f;

    extern __shared__ __half dynh[];
    __half* As = dynh;                  // 2 x [128][72]
    __half* Bs = dynh + 2 * 9216;       // 2 x [128][72]

    const int tid = threadIdx.x;
    const int lane = tid & 31, w = tid >> 5;
    const int g = lane >> 2, tg = lane & 3;
    const int wm = (w >> 1) * 64, wn = (w & 1) * 64;
    const int m0 = blockIdx.y * 128, n0 = blockIdx.x * 128;

    const uint32_t a_base0 = smaddr(As) +
        (((wm + (lane & 15)) * ST + (lane >> 4) * 8) << 1);
    const uint32_t b_base0 = smaddr(Bs) +
        (((wn + (lane & 15)) * ST + (lane >> 4) * 8) << 1);

    auto issue = [&](int s, int k0) {
#pragma unroll
        for (int t = 0; t < 8; t++) {           // A: 128x64 halves = 16 KB
            int idx = tid + t * 128;
            int row = idx >> 3, cc = (idx & 7) * 8;
            cpa16(smaddr(As + s * 9216 + row * ST + cc),
                  X + (size_t)(m0 + row) * D + k0 + cc);
        }
#pragma unroll
        for (int t = 0; t < 8; t++) {           // B: 128x64 halves
            int idx = tid + t * 128;
            int row = idx >> 3, cc = (idx & 7) * 8;
            cpa16(smaddr(Bs + s * 9216 + row * ST + cc),
                  WT + (size_t)(n0 + row) * D + k0 + cc);
        }
    };

    float c[4][8][4];
#pragma unroll
    for (int mi = 0; mi < 4; mi++)
#pragma unroll
        for (int ni = 0; ni < 8; ni++)
#pragma unroll
            for (int r = 0; r < 4; r++) c[mi][ni][r] = 0.f;

    issue(0, 0); cp_commit();

    for (int t = 0; t < 16; t++) {
        if (t + 1 < 16) { issue((t + 1) & 1, (t + 1) * 64); cp_commit(); cp_wait<1>(); }
        else cp_wait<0>();
        __syncthreads();
        const uint32_t aB = a_base0 + (t & 1) * 9216 * 2;
        const uint32_t bB = b_base0 + (t & 1) * 9216 * 2;
#pragma unroll
        for (int ks = 0; ks < 4; ks++) {
            const int kk = ks * 16;
            uint32_t a[4][4], bb[8][2];
#pragma unroll
            for (int mi = 0; mi < 4; mi++)
                ldsm4(a[mi], aB + ((mi * 16 * ST + kk) << 1));
#pragma unroll
            for (int pr = 0; pr < 4; pr++) {
                uint32_t rr[4];
                ldsm4(rr, bB + ((pr * 16 * ST + kk) << 1));
                bb[2 * pr][0] = rr[0]; bb[2 * pr][1] = rr[2];
                bb[2 * pr + 1][0] = rr[1]; bb[2 * pr + 1][1] = rr[3];
            }
#pragma unroll
            for (int mi = 0; mi < 4; mi++)
#pragma unroll
                for (int ni = 0; ni < 8; ni++)
                    mma16(c[mi][ni], a[mi], bb[ni]);
        }
        __syncthreads();
    }
    const int bblk = m0 / L, lbase = m0 % L;
    if (z < 2) {
        __half* OutHeads = (z == 0) ? Qh : Kh;
#pragma unroll
        for (int mi = 0; mi < 4; mi++)
#pragma unroll
            for (int r = 0; r < 2; r++) {
                int l = lbase + wm + mi * 16 + g + r * 8;
#pragma unroll
                for (int ni = 0; ni < 8; ni++) {
                    int n = n0 + wn + ni * 8 + tg * 2;
                    int h = n >> 6, d = n & 63;
                    *(__half2*)&OutHeads[(((size_t)bblk * H + h) * L + l) * DH + d] =
                        __floats2half2_rn((c[mi][ni][r * 2 + 0] + bias[n]) * scale,
                                          (c[mi][ni][r * 2 + 1] + bias[n + 1]) * scale);
                }
            }
    } else {
#pragma unroll
        for (int mi = 0; mi < 4; mi++)
#pragma unroll
            for (int r = 0; r < 2; r++) {
                int l = lbase + wm + mi * 16 + g + r * 8;
#pragma unroll
                for (int ni = 0; ni < 8; ni++) {
                    int n = n0 + wn + ni * 8 + tg * 2;
                    int h = n >> 6, d = n & 63;
                    size_t base = ((size_t)(bblk * H + h) * DH + d) * L + l;
                    Vt[base]     = __float2half_rn(c[mi][ni][r * 2 + 0] + bias[n]);
                    Vt[base + L] = __float2half_rn(c[mi][ni][r * 2 + 1] + bias[n + 1]);
                }
            }
    }
}

// ---------------------------------------------------------------------------
// Pass 1: per-row expsum (no max pass; scores bounded).  fp16 mma, fp32 exp.
// ---------------------------------------------------------------------------
__global__ __launch_bounds__(256, 2) void attn_stats()
{
    extern __shared__ __half dynh[];
    __half* Qs = dynh;                        // [128][72]
    __half* Ks = dynh + 9216;                 // 2 x [128][72]
    float* red = (float*)(dynh + 3 * 9216);   // [128][4]

    const int tid = threadIdx.x;
    const int lane = tid & 31, w = tid >> 5;
    const int g = lane >> 2, tg = lane & 3;
    const int wm = (w >> 2) * 64, wn = (w & 3) * 32;
    const int bh = blockIdx.y, b = bh >> 4;
    const int i0 = blockIdx.x * 128;
    const __half* Qb = g_Qh + (size_t)bh * L * DH;
    const __half* Kb = g_Kh + (size_t)bh * L * DH;
    const uint32_t* mb = g_mbits + (size_t)b * L * MW;

    const uint32_t q_base = smaddr(Qs) +
        (((wm + (lane & 15)) * ST + (lane >> 4) * 8) << 1);
    const uint32_t k_base0 = smaddr(Ks) +
        (((wn + (lane & 15)) * ST + (lane >> 4) * 8) << 1);

    auto issueK = [&](int s, int j0) {
#pragma unroll
        for (int t = 0; t < 4; t++) {
            int idx = tid + t * 256;
            int row = idx >> 3, cc = (idx & 7) * 8;
            cpa16(smaddr(Ks + s * 9216 + row * ST + cc),
                  Kb + (size_t)(j0 + row) * DH + cc);
        }
    };
#pragma unroll
    for (int t = 0; t < 4; t++) {
        int idx = tid + t * 256;
        int row = idx >> 3, cc = (idx & 7) * 8;
        cpa16(smaddr(Qs + row * ST + cc), Qb + (size_t)(i0 + row) * DH + cc);
    }
    issueK(0, 0); cp_commit();

    float l_run[4][2];
#pragma unroll
    for (int mi = 0; mi < 4; mi++)
#pragma unroll
        for (int r = 0; r < 2; r++) l_run[mi][r] = 0.f;

    for (int jt = 0; jt < 16; jt++) {
        const int j0 = jt * 128;
        if (jt + 1 < 16) { issueK((jt + 1) & 1, (jt + 1) * 128); cp_commit(); cp_wait<1>(); }
        else cp_wait<0>();
        __syncthreads();
        const uint32_t kB = k_base0 + (jt & 1) * 9216 * 2;

        float c[4][4][4];
#pragma unroll
        for (int mi = 0; mi < 4; mi++)
#pragma unroll
            for (int ni = 0; ni < 4; ni++)
#pragma unroll
                for (int r = 0; r < 4; r++) c[mi][ni][r] = 0.f;
#pragma unroll
        for (int ks = 0; ks < 4; ks++) {
            const int kk = ks * 16;
            uint32_t a[4][4], bb[4][2];
#pragma unroll
            for (int mi = 0; mi < 4; mi++)
                ldsm4(a[mi], q_base + ((mi * 16 * ST + kk) << 1));
#pragma unroll
            for (int pr = 0; pr < 2; pr++) {
                uint32_t rr[4];
                ldsm4(rr, kB + ((pr * 16 * ST + kk) << 1));
                bb[2 * pr][0] = rr[0]; bb[2 * pr][1] = rr[2];
                bb[2 * pr + 1][0] = rr[1]; bb[2 * pr + 1][1] = rr[3];
            }
#pragma unroll
            for (int mi = 0; mi < 4; mi++)
#pragma unroll
                for (int ni = 0; ni < 4; ni++)
                    mma16(c[mi][ni], a[mi], bb[ni]);
        }

#pragma unroll
        for (int mi = 0; mi < 4; mi++)
#pragma unroll
            for (int r = 0; r < 2; r++) {
                int i = i0 + wm + mi * 16 + g + r * 8;
                uint32_t word = mb[(size_t)i * MW + ((j0 + wn) >> 5)];
                float acc = 0.f;
#pragma unroll
                for (int ni = 0; ni < 4; ni++) {
                    int bit = ni * 8 + tg * 2;
                    float e0 = exp2f(c[mi][ni][r * 2 + 0] * LOG2E);
                    float e1 = exp2f(c[mi][ni][r * 2 + 1] * LOG2E);
                    acc += (word >> bit) & 1 ? e0 : 0.f;
                    acc += (word >> (bit + 1)) & 1 ? e1 : 0.f;
                }
                l_run[mi][r] += acc;
            }
        __syncthreads();
    }
#pragma unroll
    for (int mi = 0; mi < 4; mi++)
#pragma unroll
        for (int r = 0; r < 2; r++) {
            float l = l_run[mi][r];
            l += __shfl_xor_sync(0xffffffffu, l, 1);
            l += __shfl_xor_sync(0xffffffffu, l, 2);
            if ((lane & 3) == 0)
                red[(wm + mi * 16 + g + r * 8) * 4 + (w & 3)] = l;
        }
    __syncthreads();
    if (tid < 128) {
        float l = red[tid * 4 + 0] + red[tid * 4 + 1]
                + red[tid * 4 + 2] + red[tid * 4 + 3];
        g_stats[(size_t)bh * L + i0 + tid] =
            (l == 0.f) ? make_float2(-1e9f, 1.f / (float)L)
                       : make_float2(0.f, 1.f / l);
    }
}

// ---------------------------------------------------------------------------
// Pass 2: recompute scores, normalize, write att once (.cs), O = P@V.
// fp16 mma; fp32 exp; 2 CTAs/SM (smem 55 KB).
// ---------------------------------------------------------------------------
__global__ __launch_bounds__(256, 2) void attn_pv(float* __restrict__ att)
{
    extern __shared__ __half dynh[];
    __half* Ks = dynh;                    // 2 x [64][72] = 2 x 4608
    __half* Vs = dynh + 2 * 4608;         // 2 x [64][72]
    __half* Ps = dynh + 4 * 4608;         // [128][72]

    const int tid = threadIdx.x;
    const int lane = tid & 31, w = tid >> 5;
    const int g = lane >> 2, tg = lane & 3;
    const int rg = w >> 1;                 // rows rg*32..+32
    const int jg = w & 1;                  // scores j half
    const int dg = w & 1;                  // PV d half
    const int bh = blockIdx.y, b = bh >> 4, h = bh & 15;
    const int i0 = blockIdx.x * 128;
    const __half* Qb = g_Qh + (size_t)bh * L * DH;
    const __half* Kb = g_Kh + (size_t)bh * L * DH;
    const __half* Vb = g_Vt + (size_t)bh * DH * L;
    const uint32_t* mb = g_mbits + (size_t)b * L * MW;
    float* arow = att + (size_t)bh * L * L;

    // stage Q (128x64) into Ps
#pragma unroll
    for (int t = 0; t < 4; t++) {
        int idx = tid + t * 256;
        int row = idx >> 3, cc = (idx & 7) * 8;
        cpa16(smaddr(Ps + row * ST + cc), Qb + (size_t)(i0 + row) * DH + cc);
    }
    cp_commit();

    auto issueKV = [&](int s, int j0) {
#pragma unroll
        for (int t = 0; t < 2; t++) {           // K: 64x64 halves
            int idx = tid + t * 256;
            int row = idx >> 3, cc = (idx & 7) * 8;
            cpa16(smaddr(Ks + s * 4608 + row * ST + cc),
                  Kb + (size_t)(j0 + row) * DH + cc);
        }
#pragma unroll
        for (int t = 0; t < 2; t++) {           // V: 64 d-rows x 64 j
            int idx = tid + t * 256;
            int row = idx >> 3, cc = (idx & 7) * 8;
            cpa16(smaddr(Vs + s * 4608 + row * ST + cc),
                  Vb + (size_t)row * L + j0 + cc);
        }
    };
    issueKV(0, 0); cp_commit();

    cp_wait<1>();
    __syncthreads();

    uint32_t qf[2][4][4];
    {
        const uint32_t qb = smaddr(Ps) +
            (((rg * 32 + (lane & 15)) * ST + (lane >> 4) * 8) << 1);
#pragma unroll
        for (int mi = 0; mi < 2; mi++)
#pragma unroll
            for (int ks = 0; ks < 4; ks++)
                ldsm4(qf[mi][ks], qb + ((mi * 16 * ST + ks * 16) << 1));
    }

    float sm[2][2], sinv[2][2];
#pragma unroll
    for (int mi = 0; mi < 2; mi++)
#pragma unroll
        for (int r = 0; r < 2; r++) {
            float2 s = g_stats[(size_t)bh * L + i0 + rg * 32 + mi * 16 + g + r * 8];
            sm[mi][r] = s.x; sinv[mi][r] = s.y;
        }

    const uint32_t k_base0 = smaddr(Ks) +
        (((jg * 32 + (lane & 15)) * ST + (lane >> 4) * 8) << 1);
    const uint32_t v_base0 = smaddr(Vs) +
        (((dg * 32 + (lane & 15)) * ST + (lane >> 4) * 8) << 1);
    const uint32_t p_base = smaddr(Ps) +
        (((rg * 32 + (lane & 15)) * ST + (lane >> 4) * 8) << 1);

    float co[2][4][4];
#pragma unroll
    for (int mi = 0; mi < 2; mi++)
#pragma unroll
        for (int ni = 0; ni < 4; ni++)
#pragma unroll
            for (int r = 0; r < 4; r++) co[mi][ni][r] = 0.f;

    for (int ch = 0; ch < 32; ch++) {
        if (ch + 1 < 32) { issueKV((ch + 1) & 1, (ch + 1) * 64); cp_commit(); cp_wait<1>(); }
        else cp_wait<0>();
        __syncthreads();
        const uint32_t kB = k_base0 + (ch & 1) * 4608 * 2;
        const uint32_t vB = v_base0 + (ch & 1) * 4608 * 2;

        // scores: 32 rows x 32 j (jg half), k = 64
        float c2[2][4][4];
#pragma unroll
        for (int mi = 0; mi < 2; mi++)
#pragma unroll
            for (int ni = 0; ni < 4; ni++)
#pragma unroll
                for (int r = 0; r < 4; r++) c2[mi][ni][r] = 0.f;
#pragma unroll
        for (int ks = 0; ks < 4; ks++) {
            uint32_t bb[4][2];
#pragma unroll
            for (int pr = 0; pr < 2; pr++) {
                uint32_t rr[4];
                ldsm4(rr, kB + ((pr * 16 * ST + ks * 16) << 1));
                bb[2 * pr][0] = rr[0]; bb[2 * pr][1] = rr[2];
                bb[2 * pr + 1][0] = rr[1]; bb[2 * pr + 1][1] = rr[3];
            }
#pragma unroll
            for (int mi = 0; mi < 2; mi++)
#pragma unroll
                for (int ni = 0; ni < 4; ni++)
                    mma16(c2[mi][ni], qf[mi][ks], bb[ni]);
        }

        // mask + exp + normalize; write att (.cs); stage P (fp16)
        const int j0 = ch * 64;
#pragma unroll
        for (int mi = 0; mi < 2; mi++)
#pragma unroll
            for (int r = 0; r < 2; r++) {
                int rl = rg * 32 + mi * 16 + g + r * 8;
                int i = i0 + rl;
                uint32_t word = mb[(size_t)i * MW + ((j0 + jg * 32) >> 5)];
                float m = sm[mi][r], inv = sinv[mi][r];
#pragma unroll
                for (int ni = 0; ni < 4; ni++) {
                    int bit = ni * 8 + tg * 2;
                    int cl = jg * 32 + bit;
                    float s0 = (word >> bit) & 1 ? c2[mi][ni][r * 2 + 0] : -1e9f;
                    float s1 = (word >> (bit + 1)) & 1 ? c2[mi][ni][r * 2 + 1] : -1e9f;
                    float p0 = exp2f((s0 - m) * LOG2E) * inv;
                    float p1 = exp2f((s1 - m) * LOG2E) * inv;
                    st_cs_f2(arow + (size_t)i * L + j0 + cl, p0, p1);
                    *(__half2*)&Ps[rl * ST + cl] = __floats2half2_rn(p0, p1);
                }
            }
        asm volatile("bar.sync %0, %1;" :: "r"(rg + 1), "r"(64) : "memory");

        // PV: 32 rows x 32 d (dg half), k = 64 (j)
#pragma unroll
        for (int ks = 0; ks < 4; ks++) {
            uint32_t a[2][4], bb[4][2];
#pragma unroll
            for (int mi = 0; mi < 2; mi++)
                ldsm4(a[mi], p_base + ((mi * 16 * ST + ks * 16) << 1));
#pragma unroll
            for (int pr = 0; pr < 2; pr++) {
                uint32_t rr[4];
                ldsm4(rr, vB + ((pr * 16 * ST + ks * 16) << 1));
                bb[2 * pr][0] = rr[0]; bb[2 * pr][1] = rr[2];
                bb[2 * pr + 1][0] = rr[1]; bb[2 * pr + 1][1] = rr[3];
            }
#pragma unroll
            for (int mi = 0; mi < 2; mi++)
#pragma unroll
                for (int ni = 0; ni < 4; ni++)
                    mma16(co[mi][ni], a[mi], bb[ni]);
        }
        __syncthreads();
    }
#pragma unroll
    for (int mi = 0; mi < 2; mi++)
#pragma unroll
        for (int ni = 0; ni < 4; ni++) {
            int d = dg * 32 + ni * 8 + tg * 2;
            int row0 = i0 + rg * 32 + mi * 16 + g;
            *(__half2*)&g_OutH[(size_t)(b * L + row0) * D + h * DH + d] =
                __floats2half2_rn(co[mi][ni][0], co[mi][ni][1]);
            *(__half2*)&g_OutH[(size_t)(b * L + row0 + 8) * D + h * DH + d] =
                __floats2half2_rn(co[mi][ni][2], co[mi][ni][3]);
        }
}

// ---------------------------------------------------------------------------
// GEMM 4: out = OutH @ Wfc + bfc + q.  fp16, 2-stage, same structure as proj.
// ---------------------------------------------------------------------------
__global__ __launch_bounds__(128, 2) void gemm_fc(
    const float* __restrict__ Xres,
    const float* __restrict__ bias, float* __restrict__ Out)
{
    extern __shared__ __half dynh[];
    __half* As = dynh;
    __half* Bs = dynh + 2 * 9216;
    const __half* WT = g_WT + 3 * NW;

    const int tid = threadIdx.x;
    const int lane = tid & 31, w = tid >> 5;
    const int g = lane >> 2, tg = lane & 3;
    const int wm = (w >> 1) * 64, wn = (w & 1) * 64;
    const int m0 = blockIdx.y * 128, n0 = blockIdx.x * 128;

    const uint32_t a_base0 = smaddr(As) +
        (((wm + (lane & 15)) * ST + (lane >> 4) * 8) << 1);
    const uint32_t b_base0 = smaddr(Bs) +
        (((wn + (lane & 15)) * ST + (lane >> 4) * 8) << 1);

    auto issue = [&](int s, int k0) {
#pragma unroll
        for (int t = 0; t < 8; t++) {
            int idx = tid + t * 128;
            int row = idx >> 3, cc = (idx & 7) * 8;
            cpa16(smaddr(As + s * 9216 + row * ST + cc),
                  g_OutH + (size_t)(m0 + row) * D + k0 + cc);
        }
#pragma unroll
        for (int t = 0; t < 8; t++) {
            int idx = tid + t * 128;
            int row = idx >> 3, cc = (idx & 7) * 8;
            cpa16(smaddr(Bs + s * 9216 + row * ST + cc),
                  WT + (size_t)(n0 + row) * D + k0 + cc);
        }
    };

    float c[4][8][4];
#pragma unroll
    for (int mi = 0; mi < 4; mi++)
#pragma unroll
        for (int ni = 0; ni < 8; ni++)
#pragma unroll
            for (int r = 0; r < 4; r++) c[mi][ni][r] = 0.f;

    issue(0, 0); cp_commit();

    for (int t = 0; t < 16; t++) {
        if (t + 1 < 16) { issue((t + 1) & 1, (t + 1) * 64); cp_commit(); cp_wait<1>(); }
        else cp_wait<0>();
        __syncthreads();
        const uint32_t aB = a_base0 + (t & 1) * 9216 * 2;
        const uint32_t bB = b_base0 + (t & 1) * 9216 * 2;
#pragma unroll
        for (int ks = 0; ks < 4; ks++) {
            const int kk = ks * 16;
            uint32_t a[4][4], bb[8][2];
#pragma unroll
            for (int mi = 0; mi < 4; mi++)
                ldsm4(a[mi], aB + ((mi * 16 * ST + kk) << 1));
#pragma unroll
            for (int pr = 0; pr < 4; pr++) {
                uint32_t rr[4];
                ldsm4(rr, bB + ((pr * 16 * ST + kk) << 1));
                bb[2 * pr][0] = rr[0]; bb[2 * pr][1] = rr[2];
                bb[2 * pr + 1][0] = rr[1]; bb[2 * pr + 1][1] = rr[3];
            }
#pragma unroll
            for (int mi = 0; mi < 4; mi++)
#pragma unroll
                for (int ni = 0; ni < 8; ni++)
                    mma16(c[mi][ni], a[mi], bb[ni]);
        }
        __syncthreads();
    }
#pragma unroll
    for (int mi = 0; mi < 4; mi++)
#pragma unroll
        for (int r = 0; r < 2; r++) {
            int gm = m0 + wm + mi * 16 + g + r * 8;
#pragma unroll
            for (int ni = 0; ni < 8; ni++) {
                int gn = n0 + wn + ni * 8 + tg * 2;
                float2 res = *(const float2*)(Xres + (size_t)gm * D + gn);
                float2 o;
                o.x = c[mi][ni][r * 2 + 0] + bias[gn]     + res.x;
                o.y = c[mi][ni][r * 2 + 1] + bias[gn + 1] + res.y;
                *(float2*)&Out[(size_t)gm * D + gn] = o;
            }
        }
}

// ---------------------------------------------------------------------------
extern "C" void kernel_launch(void* const* d_in, const int* in_sizes, int n_in,
                              void* d_out, int out_size)
{
    const float* q    = (const float*)d_in[0];
    const float* k    = (const float*)d_in[1];
    const float* v    = (const float*)d_in[2];
    const int*   mask = (const int*)d_in[3];
    const float* Wq   = (const float*)d_in[4];
    const float* bq   = (const float*)d_in[5];
    const float* Wk   = (const float*)d_in[6];
    const float* bk   = (const float*)d_in[7];
    const float* Wv   = (const float*)d_in[8];
    const float* bv   = (const float*)d_in[9];
    const float* Wfc  = (const float*)d_in[10];
    const float* bfc  = (const float*)d_in[11];

    float* out = (float*)d_out;                      // [B, L, D]
    float* att = out + (size_t)B * L * D;            // [B, H, L, L]

    __half *Qh = nullptr, *Kh = nullptr, *Vt = nullptr;
    cudaGetSymbolAddress((void**)&Qh, g_Qh);
    cudaGetSymbolAddress((void**)&Kh, g_Kh);
    cudaGetSymbolAddress((void**)&Vt, g_Vt);

    const int smem_gemm  = 4 * 9216 * 2;                       // 73728
    const int smem_stats = 3 * 9216 * 2 + 128 * 4 * 4;         // 57344
    const int smem_pv    = (4 * 4608 + 9216) * 2;              // 55296
    cudaFuncSetAttribute(gemm_proj_all, cudaFuncAttributeMaxDynamicSharedMemorySize, smem_gemm);
    cudaFuncSetAttribute(gemm_fc,       cudaFuncAttributeMaxDynamicSharedMemorySize, smem_gemm);
    cudaFuncSetAttribute(attn_stats,    cudaFuncAttributeMaxDynamicSharedMemorySize, smem_stats);
    cudaFuncSetAttribute(attn_pv,       cudaFuncAttributeMaxDynamicSharedMemorySize, smem_pv);

    // ---- capture-legal fork: side streams join via root event --------------
    cudaEventRecord(g_ov.evRoot, 0);
    cudaStreamWaitEvent(g_ov.s1, g_ov.evRoot, 0);
    cudaStreamWaitEvent(g_ov.s2, g_ov.evRoot, 0);

    transposeW<<<dim3(32, 32, 4), 256, 0, g_ov.s1>>>(Wq, Wk, Wv, Wfc);
    cudaEventRecord(g_ov.evT, g_ov.s1);
    packmask<<<(int)((size_t)B * L * L / 256), 256, 0, g_ov.s2>>>(mask);
    cudaEventRecord(g_ov.evM, g_ov.s2);
    preround<<<(int)(3 * NX / 4 / 256), 256>>>(
        (const float4*)q, (const float4*)k, (const float4*)v);
    cudaEventRecord(g_ov.evPre, 0);

    // ---- projections: QK on s0; V forked to s1 (overlaps with stats) -------
    cudaStreamWaitEvent(0, g_ov.evT, 0);
    dim3 gqk(D / 128, ML / 128, 2);   // z = 0,1
    gemm_proj_all<<<gqk, 128, smem_gemm>>>(bq, bk, bv, Qh, Kh, Vt, 0);

    cudaStreamWaitEvent(g_ov.s1, g_ov.evPre, 0);
    dim3 gv(D / 128, ML / 128, 1);    // z = 2
    gemm_proj_all<<<gv, 128, smem_gemm, g_ov.s1>>>(bq, bk, bv, Qh, Kh, Vt, 2);
    cudaEventRecord(g_ov.evV, g_ov.s1);

    // ---- attention ----------------------------------------------------------
    cudaStreamWaitEvent(0, g_ov.evM, 0);
    dim3 ga(L / 128, BH);             // (16, 64)
    attn_stats<<<ga, 256, smem_stats>>>();

    cudaStreamWaitEvent(0, g_ov.evV, 0);
    attn_pv<<<ga, 256, smem_pv>>>(att);

    // ---- output projection --------------------------------------------------
    dim3 gf(D / 128, ML / 128);       // (8, 64)
    gemm_fc<<<gf, 128, smem_gemm>>>(q, bfc, out);
}

// round 17
// speedup vs baseline: 1.1172x; 1.0037x over previous
#include <cuda_runtime.h>
#include <cuda_fp16.h>
#include <cstdint>

namespace {
constexpr int B = 4, L = 2048, D = 1024, H = 16, DH = 64;
constexpr int BH = B * H;    // 64
constexpr int ML = B * L;    // 8192
constexpr float LOG2E = 1.4426950408889634f;
constexpr size_t NX = (size_t)ML * D;        // elems per q/k/v
constexpr size_t NW = (size_t)D * D;         // elems per W
constexpr int MW = L / 32;                   // mask words per row
constexpr int ST = 72;                       // smem row stride (halves) = 144 B
}

__device__ __half g_Qh[(size_t)B * H * L * DH];   // [bh, l, d]
__device__ __half g_Kh[(size_t)B * H * L * DH];   // [bh, l, d]
__device__ __half g_Vt[(size_t)B * H * DH * L];   // [bh, d, l] (transposed)
__device__ __half g_OutH[(size_t)B * L * H * DH]; // [b*L, h*64]
__device__ __half g_xR[3 * NX];                   // fp16 q|k|v
__device__ __half g_WT[4 * NW];                   // W^T fp16: [n][k]
__device__ uint32_t g_mbits[(size_t)B * L * MW];  // packed mask bits

// ---------------------------------------------------------------------------
// streams/events for capture-legal fork-join overlap (static init)
// ---------------------------------------------------------------------------
namespace {
struct OverlapRes {
    cudaStream_t s1, s2;
    cudaEvent_t evRoot, evT, evM;
    OverlapRes() {
        cudaStreamCreateWithFlags(&s1, cudaStreamNonBlocking);
        cudaStreamCreateWithFlags(&s2, cudaStreamNonBlocking);
        cudaEventCreateWithFlags(&evRoot, cudaEventDisableTiming);
        cudaEventCreateWithFlags(&evT,    cudaEventDisableTiming);
        cudaEventCreateWithFlags(&evM,    cudaEventDisableTiming);
    }
};
OverlapRes g_ov;
}

// ---------------------------------------------------------------------------
// helpers
// ---------------------------------------------------------------------------
__device__ __forceinline__ void mma16(float* c, const uint32_t* a, const uint32_t* b) {
    asm("mma.sync.aligned.m16n8k16.row.col.f32.f16.f16.f32 "
        "{%0,%1,%2,%3},{%4,%5,%6,%7},{%8,%9},{%0,%1,%2,%3};"
        : "+f"(c[0]), "+f"(c[1]), "+f"(c[2]), "+f"(c[3])
        : "r"(a[0]), "r"(a[1]), "r"(a[2]), "r"(a[3]), "r"(b[0]), "r"(b[1]));
}
__device__ __forceinline__ void ldsm4(uint32_t* r, uint32_t addr) {
    asm volatile("ldmatrix.sync.aligned.m8n8.x4.shared.b16 {%0,%1,%2,%3}, [%4];"
                 : "=r"(r[0]), "=r"(r[1]), "=r"(r[2]), "=r"(r[3]) : "r"(addr));
}
__device__ __forceinline__ uint32_t smaddr(const void* p) {
    return (uint32_t)__cvta_generic_to_shared(p);
}
__device__ __forceinline__ void cpa16(uint32_t dst, const void* src) {
    asm volatile("cp.async.ca.shared.global [%0], [%1], 16;\n" :: "r"(dst), "l"(src));
}
__device__ __forceinline__ void cp_commit() {
    asm volatile("cp.async.commit_group;\n");
}
template <int N> __device__ __forceinline__ void cp_wait() {
    asm volatile("cp.async.wait_group %0;\n" :: "n"(N));
}
__device__ __forceinline__ void st_cs_f2(float* p, float x, float y) {
    asm volatile("st.global.cs.v2.f32 [%0], {%1, %2};"
                 :: "l"(p), "f"(x), "f"(y) : "memory");
}

// ---------------------------------------------------------------------------
// Pre-convert q/k/v to fp16 (rne), once.
// ---------------------------------------------------------------------------
__global__ __launch_bounds__(256) void preround(
    const float4* __restrict__ q, const float4* __restrict__ k,
    const float4* __restrict__ v)
{
    const size_t NX4 = NX / 4;
    size_t i = (size_t)blockIdx.x * 256 + threadIdx.x;
    const float4* src = (i < NX4) ? q : (i < 2 * NX4) ? k : v;
    size_t off = (i < NX4) ? i : (i < 2 * NX4) ? i - NX4 : i - 2 * NX4;
    float4 x = src[off];
    ((__half2*)g_xR)[2 * i]     = __floats2half2_rn(x.x, x.y);
    ((__half2*)g_xR)[2 * i + 1] = __floats2half2_rn(x.z, x.w);
}

// ---------------------------------------------------------------------------
// Transpose + convert weights: g_WT[z][n][k] = fp16(W_z[k][n]).
// ---------------------------------------------------------------------------
__global__ __launch_bounds__(256) void transposeW(
    const float* __restrict__ wq, const float* __restrict__ wk,
    const float* __restrict__ wv, const float* __restrict__ wfc)
{
    __shared__ float t[32][33];
    const int z = blockIdx.z;
    const float* src = (z == 0) ? wq : (z == 1) ? wk : (z == 2) ? wv : wfc;
    const int k0 = blockIdx.y * 32, n0 = blockIdx.x * 32;
    const int x = threadIdx.x & 31, y = threadIdx.x >> 5;  // 32 x 8
#pragma unroll
    for (int j = 0; j < 4; j++)
        t[y + j * 8][x] = src[(size_t)(k0 + y + j * 8) * D + n0 + x];
    __syncthreads();
#pragma unroll
    for (int j = 0; j < 4; j++)
        g_WT[(size_t)z * NW + (size_t)(n0 + y + j * 8) * D + k0 + x] =
            __float2half_rn(t[x][y + j * 8]);
}

// ---------------------------------------------------------------------------
// Pack int32 mask -> bitmask.
// ---------------------------------------------------------------------------
__global__ __launch_bounds__(256) void packmask(const int* __restrict__ mask)
{
    size_t i = (size_t)blockIdx.x * 256 + threadIdx.x;
    int mv = mask[i];
    uint32_t bal = __ballot_sync(0xffffffffu, mv != 0);
    if ((threadIdx.x & 31) == 0) g_mbits[i >> 5] = bal;
}

// ---------------------------------------------------------------------------
// GEMM 1: QKV projections (z = blockIdx.z).  fp16 mma m16n8k16.
// 128 thr, 4 warps, warp tile 64x64, ktile 64, cp.async 2-stage.
// V stored TRANSPOSED [bh, d, l].
// ---------------------------------------------------------------------------
__global__ __launch_bounds__(128, 2) void gemm_proj_all(
    const float* __restrict__ bq, const float* __restrict__ bk,
    const float* __restrict__ bv,
    __half* __restrict__ Qh, __half* __restrict__ Kh, __half* __restrict__ Vt)
{
    const int z = blockIdx.z;
    const __half* X = g_xR + (size_t)z * NX;
    const __half* WT = g_WT + (size_t)z * NW;
    const float* bias = (z == 0) ? bq : (z == 1) ? bk : bv;
    const float scale = (z == 0) ? 0.125f : 1.0f;

    extern __shared__ __half dynh[];
    __half* As = dynh;                  // 2 x [128][72]
    __half* Bs = dynh + 2 * 9216;       // 2 x [128][72]

    const int tid = threadIdx.x;
    const int lane = tid & 31, w = tid >> 5;
    const int g = lane >> 2, tg = lane & 3;
    const int wm = (w >> 1) * 64, wn = (w & 1) * 64;
    const int m0 = blockIdx.y * 128, n0 = blockIdx.x * 128;

    const uint32_t a_base0 = smaddr(As) +
        (((wm + (lane & 15)) * ST + (lane >> 4) * 8) << 1);
    const uint32_t b_base0 = smaddr(Bs) +
        (((wn + (lane & 15)) * ST + (lane >> 4) * 8) << 1);

    auto issue = [&](int s, int k0) {
#pragma unroll
        for (int t = 0; t < 8; t++) {           // A: 128x64 halves = 16 KB
            int idx = tid + t * 128;
            int row = idx >> 3, cc = (idx & 7) * 8;
            cpa16(smaddr(As + s * 9216 + row * ST + cc),
                  X + (size_t)(m0 + row) * D + k0 + cc);
        }
#pragma unroll
        for (int t = 0; t < 8; t++) {           // B: 128x64 halves
            int idx = tid + t * 128;
            int row = idx >> 3, cc = (idx & 7) * 8;
            cpa16(smaddr(Bs + s * 9216 + row * ST + cc),
                  WT + (size_t)(n0 + row) * D + k0 + cc);
        }
    };

    float c[4][8][4];
#pragma unroll
    for (int mi = 0; mi < 4; mi++)
#pragma unroll
        for (int ni = 0; ni < 8; ni++)
#pragma unroll
            for (int r = 0; r < 4; r++) c[mi][ni][r] = 0.f;

    issue(0, 0); cp_commit();

    for (int t = 0; t < 16; t++) {
        if (t + 1 < 16) { issue((t + 1) & 1, (t + 1) * 64); cp_commit(); cp_wait<1>(); }
        else cp_wait<0>();
        __syncthreads();
        const uint32_t aB = a_base0 + (t & 1) * 9216 * 2;
        const uint32_t bB = b_base0 + (t & 1) * 9216 * 2;
#pragma unroll
        for (int ks = 0; ks < 4; ks++) {
            const int kk = ks * 16;
            uint32_t a[4][4], bb[8][2];
#pragma unroll
            for (int mi = 0; mi < 4; mi++)
                ldsm4(a[mi], aB + ((mi * 16 * ST + kk) << 1));
#pragma unroll
            for (int pr = 0; pr < 4; pr++) {
                uint32_t rr[4];
                ldsm4(rr, bB + ((pr * 16 * ST + kk) << 1));
                bb[2 * pr][0] = rr[0]; bb[2 * pr][1] = rr[2];
                bb[2 * pr + 1][0] = rr[1]; bb[2 * pr + 1][1] = rr[3];
            }
#pragma unroll
            for (int mi = 0; mi < 4; mi++)
#pragma unroll
                for (int ni = 0; ni < 8; ni++)
                    mma16(c[mi][ni], a[mi], bb[ni]);
        }
        __syncthreads();
    }
    const int bblk = m0 / L, lbase = m0 % L;
    if (z < 2) {
        __half* OutHeads = (z == 0) ? Qh : Kh;
#pragma unroll
        for (int mi = 0; mi < 4; mi++)
#pragma unroll
            for (int r = 0; r < 2; r++) {
                int l = lbase + wm + mi * 16 + g + r * 8;
#pragma unroll
                for (int ni = 0; ni < 8; ni++) {
                    int n = n0 + wn + ni * 8 + tg * 2;
                    int h = n >> 6, d = n & 63;
                    *(__half2*)&OutHeads[(((size_t)bblk * H + h) * L + l) * DH + d] =
                        __floats2half2_rn((c[mi][ni][r * 2 + 0] + bias[n]) * scale,
                                          (c[mi][ni][r * 2 + 1] + bias[n + 1]) * scale);
                }
            }
    } else {
#pragma unroll
        for (int mi = 0; mi < 4; mi++)
#pragma unroll
            for (int r = 0; r < 2; r++) {
                int l = lbase + wm + mi * 16 + g + r * 8;
#pragma unroll
                for (int ni = 0; ni < 8; ni++) {
                    int n = n0 + wn + ni * 8 + tg * 2;
                    int h = n >> 6, d = n & 63;
                    size_t base = ((size_t)(bblk * H + h) * DH + d) * L + l;
                    Vt[base]     = __float2half_rn(c[mi][ni][r * 2 + 0] + bias[n]);
                    Vt[base + L] = __float2half_rn(c[mi][ni][r * 2 + 1] + bias[n + 1]);
                }
            }
    }
}

// ---------------------------------------------------------------------------
// FUSED attention: phase 1 computes per-row expsum (no max; scores bounded),
// phase 2 recomputes scores, normalizes, writes att once (.cs), O = P@V.
// Q staged ONCE in smem and reused across phases; stats pass via smem.
// smem: Qs[128][72] | B0 (ph1: K 2x[128][72]; ph2: K 2x[64][72] + V 2x[64][72])
//       | Ps[128][72] | red[128][4] f32 | sstat[128] float2.
// ---------------------------------------------------------------------------
__global__ __launch_bounds__(256, 2) void attn_fused(float* __restrict__ att)
{
    extern __shared__ __half dynh[];
    __half* Qs = dynh;                       // [128][72] = 9216 halves
    __half* B0 = dynh + 9216;                // 18432 halves (phase-dependent)
    __half* Ps = dynh + 9216 + 18432;        // [128][72] (phase 2)
    float* red = (float*)(dynh + 36864);     // [128][4]
    float2* sstat = (float2*)(red + 512);    // [128]

    const int tid = threadIdx.x;
    const int lane = tid & 31, w = tid >> 5;
    const int g = lane >> 2, tg = lane & 3;
    const int bh = blockIdx.y, b = bh >> 4, h = bh & 15;
    const int i0 = blockIdx.x * 128;
    const __half* Qb = g_Qh + (size_t)bh * L * DH;
    const __half* Kb = g_Kh + (size_t)bh * L * DH;
    const __half* Vb = g_Vt + (size_t)bh * DH * L;
    const uint32_t* mb = g_mbits + (size_t)b * L * MW;
    float* arow = att + (size_t)bh * L * L;

    // stage Q (128x64) into Qs — used by BOTH phases
#pragma unroll
    for (int t = 0; t < 4; t++) {
        int idx = tid + t * 256;
        int row = idx >> 3, cc = (idx & 7) * 8;
        cpa16(smaddr(Qs + row * ST + cc), Qb + (size_t)(i0 + row) * DH + cc);
    }

    // =========================== PHASE 1: stats ===========================
    {
        const int wm1 = (w >> 2) * 64, wn1 = (w & 3) * 32;
        const uint32_t q_base = smaddr(Qs) +
            (((wm1 + (lane & 15)) * ST + (lane >> 4) * 8) << 1);
        const uint32_t k_base0 = smaddr(B0) +
            (((wn1 + (lane & 15)) * ST + (lane >> 4) * 8) << 1);

        auto issueK = [&](int s, int j0) {
#pragma unroll
            for (int t = 0; t < 4; t++) {
                int idx = tid + t * 256;
                int row = idx >> 3, cc = (idx & 7) * 8;
                cpa16(smaddr(B0 + s * 9216 + row * ST + cc),
                      Kb + (size_t)(j0 + row) * DH + cc);
            }
        };
        issueK(0, 0); cp_commit();       // Q + K0 in group 1

        float l_run[4][2];
#pragma unroll
        for (int mi = 0; mi < 4; mi++)
#pragma unroll
            for (int r = 0; r < 2; r++) l_run[mi][r] = 0.f;

        for (int jt = 0; jt < 16; jt++) {
            const int j0 = jt * 128;
            if (jt + 1 < 16) { issueK((jt + 1) & 1, (jt + 1) * 128); cp_commit(); cp_wait<1>(); }
            else cp_wait<0>();
            __syncthreads();
            const uint32_t kB = k_base0 + (jt & 1) * 9216 * 2;

            float c[4][4][4];
#pragma unroll
            for (int mi = 0; mi < 4; mi++)
#pragma unroll
                for (int ni = 0; ni < 4; ni++)
#pragma unroll
                    for (int r = 0; r < 4; r++) c[mi][ni][r] = 0.f;
#pragma unroll
            for (int ks = 0; ks < 4; ks++) {
                const int kk = ks * 16;
                uint32_t a[4][4], bb[4][2];
#pragma unroll
                for (int mi = 0; mi < 4; mi++)
                    ldsm4(a[mi], q_base + ((mi * 16 * ST + kk) << 1));
#pragma unroll
                for (int pr = 0; pr < 2; pr++) {
                    uint32_t rr[4];
                    ldsm4(rr, kB + ((pr * 16 * ST + kk) << 1));
                    bb[2 * pr][0] = rr[0]; bb[2 * pr][1] = rr[2];
                    bb[2 * pr + 1][0] = rr[1]; bb[2 * pr + 1][1] = rr[3];
                }
#pragma unroll
                for (int mi = 0; mi < 4; mi++)
#pragma unroll
                    for (int ni = 0; ni < 4; ni++)
                        mma16(c[mi][ni], a[mi], bb[ni]);
            }

#pragma unroll
            for (int mi = 0; mi < 4; mi++)
#pragma unroll
                for (int r = 0; r < 2; r++) {
                    int i = i0 + wm1 + mi * 16 + g + r * 8;
                    uint32_t word = mb[(size_t)i * MW + ((j0 + wn1) >> 5)];
                    float acc = 0.f;
#pragma unroll
                    for (int ni = 0; ni < 4; ni++) {
                        int bit = ni * 8 + tg * 2;
                        float e0 = exp2f(c[mi][ni][r * 2 + 0] * LOG2E);
                        float e1 = exp2f(c[mi][ni][r * 2 + 1] * LOG2E);
                        acc += (word >> bit) & 1 ? e0 : 0.f;
                        acc += (word >> (bit + 1)) & 1 ? e1 : 0.f;
                    }
                    l_run[mi][r] += acc;
                }
            __syncthreads();
        }
#pragma unroll
        for (int mi = 0; mi < 4; mi++)
#pragma unroll
            for (int r = 0; r < 2; r++) {
                float l = l_run[mi][r];
                l += __shfl_xor_sync(0xffffffffu, l, 1);
                l += __shfl_xor_sync(0xffffffffu, l, 2);
                if ((lane & 3) == 0)
                    red[(wm1 + mi * 16 + g + r * 8) * 4 + (w & 3)] = l;
            }
        __syncthreads();
        if (tid < 128) {
            float l = red[tid * 4 + 0] + red[tid * 4 + 1]
                    + red[tid * 4 + 2] + red[tid * 4 + 3];
            sstat[tid] = (l == 0.f) ? make_float2(-1e9f, 1.f / (float)L)
                                    : make_float2(0.f, 1.f / l);
        }
        __syncthreads();
    }

    // =========================== PHASE 2: PV ==============================
    {
        __half* Ks = B0;                  // 2 x [64][72]
        __half* Vs = B0 + 2 * 4608;       // 2 x [64][72]
        const int rg = w >> 1;            // rows rg*32..+32
        const int jg = w & 1;             // scores j half
        const int dg = w & 1;             // PV d half

        auto issueKV = [&](int s, int j0) {
#pragma unroll
            for (int t = 0; t < 2; t++) {       // K: 64x64 halves
                int idx = tid + t * 256;
                int row = idx >> 3, cc = (idx & 7) * 8;
                cpa16(smaddr(Ks + s * 4608 + row * ST + cc),
                      Kb + (size_t)(j0 + row) * DH + cc);
            }
#pragma unroll
            for (int t = 0; t < 2; t++) {       // V: 64 d-rows x 64 j
                int idx = tid + t * 256;
                int row = idx >> 3, cc = (idx & 7) * 8;
                cpa16(smaddr(Vs + s * 4608 + row * ST + cc),
                      Vb + (size_t)row * L + j0 + cc);
            }
        };
        issueKV(0, 0); cp_commit();

        // hoist Q fragments (Qs intact from phase 1)
        uint32_t qf[2][4][4];
        {
            const uint32_t qb = smaddr(Qs) +
                (((rg * 32 + (lane & 15)) * ST + (lane >> 4) * 8) << 1);
#pragma unroll
            for (int mi = 0; mi < 2; mi++)
#pragma unroll
                for (int ks = 0; ks < 4; ks++)
                    ldsm4(qf[mi][ks], qb + ((mi * 16 * ST + ks * 16) << 1));
        }

        float sm[2][2], sinv[2][2];
#pragma unroll
        for (int mi = 0; mi < 2; mi++)
#pragma unroll
            for (int r = 0; r < 2; r++) {
                float2 s = sstat[rg * 32 + mi * 16 + g + r * 8];
                sm[mi][r] = s.x; sinv[mi][r] = s.y;
            }

        const uint32_t k_base0 = smaddr(Ks) +
            (((jg * 32 + (lane & 15)) * ST + (lane >> 4) * 8) << 1);
        const uint32_t v_base0 = smaddr(Vs) +
            (((dg * 32 + (lane & 15)) * ST + (lane >> 4) * 8) << 1);
        const uint32_t p_base = smaddr(Ps) +
            (((rg * 32 + (lane & 15)) * ST + (lane >> 4) * 8) << 1);

        float co[2][4][4];
#pragma unroll
        for (int mi = 0; mi < 2; mi++)
#pragma unroll
            for (int ni = 0; ni < 4; ni++)
#pragma unroll
                for (int r = 0; r < 4; r++) co[mi][ni][r] = 0.f;

        for (int ch = 0; ch < 32; ch++) {
            if (ch + 1 < 32) { issueKV((ch + 1) & 1, (ch + 1) * 64); cp_commit(); cp_wait<1>(); }
            else cp_wait<0>();
            __syncthreads();
            const uint32_t kB = k_base0 + (ch & 1) * 4608 * 2;
            const uint32_t vB = v_base0 + (ch & 1) * 4608 * 2;

            // scores: 32 rows x 32 j (jg half), k = 64
            float c2[2][4][4];
#pragma unroll
            for (int mi = 0; mi < 2; mi++)
#pragma unroll
                for (int ni = 0; ni < 4; ni++)
#pragma unroll
                    for (int r = 0; r < 4; r++) c2[mi][ni][r] = 0.f;
#pragma unroll
            for (int ks = 0; ks < 4; ks++) {
                uint32_t bb[4][2];
#pragma unroll
                for (int pr = 0; pr < 2; pr++) {
                    uint32_t rr[4];
                    ldsm4(rr, kB + ((pr * 16 * ST + ks * 16) << 1));
                    bb[2 * pr][0] = rr[0]; bb[2 * pr][1] = rr[2];
                    bb[2 * pr + 1][0] = rr[1]; bb[2 * pr + 1][1] = rr[3];
                }
#pragma unroll
                for (int mi = 0; mi < 2; mi++)
#pragma unroll
                    for (int ni = 0; ni < 4; ni++)
                        mma16(c2[mi][ni], qf[mi][ks], bb[ni]);
            }

            // mask + exp + normalize; write att (.cs); stage P (fp16)
            const int j0 = ch * 64;
#pragma unroll
            for (int mi = 0; mi < 2; mi++)
#pragma unroll
                for (int r = 0; r < 2; r++) {
                    int rl = rg * 32 + mi * 16 + g + r * 8;
                    int i = i0 + rl;
                    uint32_t word = mb[(size_t)i * MW + ((j0 + jg * 32) >> 5)];
                    float m = sm[mi][r], inv = sinv[mi][r];
#pragma unroll
                    for (int ni = 0; ni < 4; ni++) {
                        int bit = ni * 8 + tg * 2;
                        int cl = jg * 32 + bit;
                        float s0 = (word >> bit) & 1 ? c2[mi][ni][r * 2 + 0] : -1e9f;
                        float s1 = (word >> (bit + 1)) & 1 ? c2[mi][ni][r * 2 + 1] : -1e9f;
                        float p0 = exp2f((s0 - m) * LOG2E) * inv;
                        float p1 = exp2f((s1 - m) * LOG2E) * inv;
                        st_cs_f2(arow + (size_t)i * L + j0 + cl, p0, p1);
                        *(__half2*)&Ps[rl * ST + cl] = __floats2half2_rn(p0, p1);
                    }
                }
            asm volatile("bar.sync %0, %1;" :: "r"(rg + 1), "r"(64) : "memory");

            // PV: 32 rows x 32 d (dg half), k = 64 (j)
#pragma unroll
            for (int ks = 0; ks < 4; ks++) {
                uint32_t a[2][4], bb[4][2];
#pragma unroll
                for (int mi = 0; mi < 2; mi++)
                    ldsm4(a[mi], p_base + ((mi * 16 * ST + ks * 16) << 1));
#pragma unroll
                for (int pr = 0; pr < 2; pr++) {
                    uint32_t rr[4];
                    ldsm4(rr, vB + ((pr * 16 * ST + ks * 16) << 1));
                    bb[2 * pr][0] = rr[0]; bb[2 * pr][1] = rr[2];
                    bb[2 * pr + 1][0] = rr[1]; bb[2 * pr + 1][1] = rr[3];
                }
#pragma unroll
                for (int mi = 0; mi < 2; mi++)
#pragma unroll
                    for (int ni = 0; ni < 4; ni++)
                        mma16(co[mi][ni], a[mi], bb[ni]);
            }
            __syncthreads();
        }
#pragma unroll
        for (int mi = 0; mi < 2; mi++)
#pragma unroll
            for (int ni = 0; ni < 4; ni++) {
                int d = dg * 32 + ni * 8 + tg * 2;
                int row0 = i0 + rg * 32 + mi * 16 + g;
                *(__half2*)&g_OutH[(size_t)(b * L + row0) * D + h * DH + d] =
                    __floats2half2_rn(co[mi][ni][0], co[mi][ni][1]);
                *(__half2*)&g_OutH[(size_t)(b * L + row0 + 8) * D + h * DH + d] =
                    __floats2half2_rn(co[mi][ni][2], co[mi][ni][3]);
            }
    }
}

// ---------------------------------------------------------------------------
// GEMM 4: out = OutH @ Wfc + bfc + q.  fp16, 2-stage, same structure as proj.
// ---------------------------------------------------------------------------
__global__ __launch_bounds__(128, 2) void gemm_fc(
    const float* __restrict__ Xres,
    const float* __restrict__ bias, float* __restrict__ Out)
{
    extern __shared__ __half dynh[];
    __half* As = dynh;
    __half* Bs = dynh + 2 * 9216;
    const __half* WT = g_WT + 3 * NW;

    const int tid = threadIdx.x;
    const int lane = tid & 31, w = tid >> 5;
    const int g = lane >> 2, tg = lane & 3;
    const int wm = (w >> 1) * 64, wn = (w & 1) * 64;
    const int m0 = blockIdx.y * 128, n0 = blockIdx.x * 128;

    const uint32_t a_base0 = smaddr(As) +
        (((wm + (lane & 15)) * ST + (lane >> 4) * 8) << 1);
    const uint32_t b_base0 = smaddr(Bs) +
        (((wn + (lane & 15)) * ST + (lane >> 4) * 8) << 1);

    auto issue = [&](int s, int k0) {
#pragma unroll
        for (int t = 0; t < 8; t++) {
            int idx = tid + t * 128;
            int row = idx >> 3, cc = (idx & 7) * 8;
            cpa16(smaddr(As + s * 9216 + row * ST + cc),
                  g_OutH + (size_t)(m0 + row) * D + k0 + cc);
        }
#pragma unroll
        for (int t = 0; t < 8; t++) {
            int idx = tid + t * 128;
            int row = idx >> 3, cc = (idx & 7) * 8;
            cpa16(smaddr(Bs + s * 9216 + row * ST + cc),
                  WT + (size_t)(n0 + row) * D + k0 + cc);
        }
    };

    float c[4][8][4];
#pragma unroll
    for (int mi = 0; mi < 4; mi++)
#pragma unroll
        for (int ni = 0; ni < 8; ni++)
#pragma unroll
            for (int r = 0; r < 4; r++) c[mi][ni][r] = 0.f;

    issue(0, 0); cp_commit();

    for (int t = 0; t < 16; t++) {
        if (t + 1 < 16) { issue((t + 1) & 1, (t + 1) * 64); cp_commit(); cp_wait<1>(); }
        else cp_wait<0>();
        __syncthreads();
        const uint32_t aB = a_base0 + (t & 1) * 9216 * 2;
        const uint32_t bB = b_base0 + (t & 1) * 9216 * 2;
#pragma unroll
        for (int ks = 0; ks < 4; ks++) {
            const int kk = ks * 16;
            uint32_t a[4][4], bb[8][2];
#pragma unroll
            for (int mi = 0; mi < 4; mi++)
                ldsm4(a[mi], aB + ((mi * 16 * ST + kk) << 1));
#pragma unroll
            for (int pr = 0; pr < 4; pr++) {
                uint32_t rr[4];
                ldsm4(rr, bB + ((pr * 16 * ST + kk) << 1));
                bb[2 * pr][0] = rr[0]; bb[2 * pr][1] = rr[2];
                bb[2 * pr + 1][0] = rr[1]; bb[2 * pr + 1][1] = rr[3];
            }
#pragma unroll
            for (int mi = 0; mi < 4; mi++)
#pragma unroll
                for (int ni = 0; ni < 8; ni++)
                    mma16(c[mi][ni], a[mi], bb[ni]);
        }
        __syncthreads();
    }
#pragma unroll
    for (int mi = 0; mi < 4; mi++)
#pragma unroll
        for (int r = 0; r < 2; r++) {
            int gm = m0 + wm + mi * 16 + g + r * 8;
#pragma unroll
            for (int ni = 0; ni < 8; ni++) {
                int gn = n0 + wn + ni * 8 + tg * 2;
                float2 res = *(const float2*)(Xres + (size_t)gm * D + gn);
                float2 o;
                o.x = c[mi][ni][r * 2 + 0] + bias[gn]     + res.x;
                o.y = c[mi][ni][r * 2 + 1] + bias[gn + 1] + res.y;
                *(float2*)&Out[(size_t)gm * D + gn] = o;
            }
        }
}

// ---------------------------------------------------------------------------
extern "C" void kernel_launch(void* const* d_in, const int* in_sizes, int n_in,
                              void* d_out, int out_size)
{
    const float* q    = (const float*)d_in[0];
    const float* k    = (const float*)d_in[1];
    const float* v    = (const float*)d_in[2];
    const int*   mask = (const int*)d_in[3];
    const float* Wq   = (const float*)d_in[4];
    const float* bq   = (const float*)d_in[5];
    const float* Wk   = (const float*)d_in[6];
    const float* bk   = (const float*)d_in[7];
    const float* Wv   = (const float*)d_in[8];
    const float* bv   = (const float*)d_in[9];
    const float* Wfc  = (const float*)d_in[10];
    const float* bfc  = (const float*)d_in[11];

    float* out = (float*)d_out;                      // [B, L, D]
    float* att = out + (size_t)B * L * D;            // [B, H, L, L]

    __half *Qh = nullptr, *Kh = nullptr, *Vt = nullptr;
    cudaGetSymbolAddress((void**)&Qh, g_Qh);
    cudaGetSymbolAddress((void**)&Kh, g_Kh);
    cudaGetSymbolAddress((void**)&Vt, g_Vt);

    const int smem_gemm = 4 * 9216 * 2;                        // 73728
    const int smem_att  = 36864 * 2 + 512 * 4 + 128 * 8;       // 76800
    cudaFuncSetAttribute(gemm_proj_all, cudaFuncAttributeMaxDynamicSharedMemorySize, smem_gemm);
    cudaFuncSetAttribute(gemm_fc,       cudaFuncAttributeMaxDynamicSharedMemorySize, smem_gemm);
    cudaFuncSetAttribute(attn_fused,    cudaFuncAttributeMaxDynamicSharedMemorySize, smem_att);

    // ---- capture-legal fork: side streams join via root event --------------
    cudaEventRecord(g_ov.evRoot, 0);
    cudaStreamWaitEvent(g_ov.s1, g_ov.evRoot, 0);
    cudaStreamWaitEvent(g_ov.s2, g_ov.evRoot, 0);

    transposeW<<<dim3(32, 32, 4), 256, 0, g_ov.s1>>>(Wq, Wk, Wv, Wfc);
    cudaEventRecord(g_ov.evT, g_ov.s1);
    packmask<<<(int)((size_t)B * L * L / 256), 256, 0, g_ov.s2>>>(mask);
    cudaEventRecord(g_ov.evM, g_ov.s2);
    preround<<<(int)(3 * NX / 4 / 256), 256>>>(
        (const float4*)q, (const float4*)k, (const float4*)v);

    // ---- projections: all three on stream 0 --------------------------------
    cudaStreamWaitEvent(0, g_ov.evT, 0);
    dim3 gp(D / 128, ML / 128, 3);    // (8, 64, 3)
    gemm_proj_all<<<gp, 128, smem_gemm>>>(bq, bk, bv, Qh, Kh, Vt);

    // ---- fused attention ----------------------------------------------------
    cudaStreamWaitEvent(0, g_ov.evM, 0);
    dim3 ga(L / 128, BH);             // (16, 64)
    attn_fused<<<ga, 256, smem_att>>>(att);

    // ---- output projection --------------------------------------------------
    dim3 gf(D / 128, ML / 128);       // (8, 64)
    gemm_fc<<<gf, 128, smem_gemm>>>(q, bfc, out);
}